// round 1
// baseline (speedup 1.0000x reference)
#include <cuda_runtime.h>
#include <cuda_bf16.h>
#include <math.h>

// Problem constants
#define BB 4
#define SS 1024
#define DD 768
#define HH 12
#define DH 64
#define D3 2304   // 3*D

// Scratch (no runtime allocation allowed)
__device__ float g_qkv[(long long)BB * SS * D3];          // [B,S,3D]  37.7 MB
__device__ float g_attn[(long long)BB * HH * SS * SS];    // [B,H,S,S] 192 MB
__device__ float g_obuf[(long long)BB * SS * DD];         // [B,S,D]   12.6 MB

// ---------------------------------------------------------------------------
// Generic batched SGEMM: C = alpha * A @ op(B) + bias
//   A row-major [M,K] (lda), B row-major [K,N] (ldb) or, if TRANSB, [N,K] (ldb)
//   batch index z -> (b = z/H, h = z%H); per-batch pointer offsets via strides.
//   Tile: BM=128, BN=64, BK=16, 256 threads, 8x4 per thread.
//   Requires M%128==0, N%64==0, K%16==0 (true for all uses here).
// ---------------------------------------------------------------------------
template <bool TRANSB>
__global__ __launch_bounds__(256)
void sgemm_k(const float* __restrict__ A, const float* __restrict__ B,
             float* __restrict__ C, const float* __restrict__ bias,
             int M, int N, int K, int lda, int ldb, int ldc, float alpha,
             int H, long long sAb, long long sAh, long long sBb, long long sBh,
             long long sCb, long long sCh)
{
    constexpr int BM = 128, BN = 64, BK = 16, TM = 8, TN = 4;
    __shared__ float As[BK][BM + 4];
    __shared__ float Bs[BK][BN + 4];

    const int bh = blockIdx.z;
    const int b = bh / H, h = bh % H;
    A += b * sAb + h * sAh;
    B += b * sBb + h * sBh;
    C += b * sCb + h * sCh;

    const int m0 = blockIdx.y * BM;
    const int n0 = blockIdx.x * BN;
    const int tid = threadIdx.x;
    const int tx = tid & 15;         // 0..15 -> N
    const int ty = tid >> 4;         // 0..15 -> M

    float acc[TM][TN];
#pragma unroll
    for (int i = 0; i < TM; i++)
#pragma unroll
        for (int j = 0; j < TN; j++) acc[i][j] = 0.f;

    for (int kt = 0; kt < K; kt += BK) {
        // Load A tile: BM*BK = 2048 elems, 8 per thread
#pragma unroll
        for (int i = 0; i < 8; i++) {
            int idx = tid + i * 256;
            int r = idx >> 4;        // m within tile
            int c = idx & 15;        // k within tile
            As[c][r] = A[(long long)(m0 + r) * lda + (kt + c)];
        }
        // Load B tile: BK*BN = 1024 elems, 4 per thread
        if (!TRANSB) {
#pragma unroll
            for (int i = 0; i < 4; i++) {
                int idx = tid + i * 256;
                int r = idx >> 6;    // k
                int c = idx & 63;    // n
                Bs[r][c] = B[(long long)(kt + r) * ldb + (n0 + c)];
            }
        } else {
#pragma unroll
            for (int i = 0; i < 4; i++) {
                int idx = tid + i * 256;
                int n = idx >> 4;    // n
                int c = idx & 15;    // k
                Bs[c][n] = B[(long long)(n0 + n) * ldb + (kt + c)];
            }
        }
        __syncthreads();

#pragma unroll
        for (int k = 0; k < BK; k++) {
            float ra[TM], rb[TN];
#pragma unroll
            for (int i = 0; i < TM; i++) ra[i] = As[k][ty * TM + i];
#pragma unroll
            for (int j = 0; j < TN; j++) rb[j] = Bs[k][tx * TN + j];
#pragma unroll
            for (int i = 0; i < TM; i++)
#pragma unroll
                for (int j = 0; j < TN; j++) acc[i][j] += ra[i] * rb[j];
        }
        __syncthreads();
    }

#pragma unroll
    for (int i = 0; i < TM; i++) {
        int m = m0 + ty * TM + i;
#pragma unroll
        for (int j = 0; j < TN; j++) {
            int n = n0 + tx * TN + j;
            float v = alpha * acc[i][j];
            if (bias) v += bias[n];
            C[(long long)m * ldc + n] = v;
        }
    }
}

// ---------------------------------------------------------------------------
// Fused talking-heads: pre-mix (Wl,bl) -> softmax over k -> post-mix (Ww,bw)
// One block per (b,q). smem: sA[12][1024] in, sP[12][1024] mixed, weights.
// In-place update of g_attn slice [b, :, q, :].
// ---------------------------------------------------------------------------
__global__ __launch_bounds__(256)
void mix_softmax_k(float* __restrict__ attn,
                   const float* __restrict__ Wl, const float* __restrict__ bl,
                   const float* __restrict__ Ww, const float* __restrict__ bw)
{
    extern __shared__ float sm[];
    float* sA  = sm;                 // 12*1024
    float* sP  = sA + HH * SS;       // 12*1024
    float* sWl = sP + HH * SS;       // 144
    float* sWw = sWl + HH * HH;      // 144
    float* sbl = sWw + HH * HH;      // 12
    float* sbw = sbl + HH;           // 12

    const int blk = blockIdx.x;
    const int b = blk >> 10;
    const int q = blk & 1023;
    const int tid = threadIdx.x;

    for (int i = tid; i < HH * HH; i += 256) { sWl[i] = Wl[i]; sWw[i] = Ww[i]; }
    if (tid < HH) { sbl[tid] = bl[tid]; sbw[tid] = bw[tid]; }

    // Load logits rows for all heads: attn[(b*12+h)*S*S + q*S + k]
    for (int idx = tid; idx < HH * SS; idx += 256) {
        int h = idx >> 10;
        int k = idx & 1023;
        sA[idx] = attn[((long long)(b * HH + h) << 20) + ((long long)q << 10) + k];
    }
    __syncthreads();

    // Pre-softmax mix: sP[g][k] = bl[g] + sum_h sA[h][k] * Wl[h][g]
    for (int idx = tid; idx < HH * SS; idx += 256) {
        int g = idx >> 10;
        int k = idx & 1023;
        float v = sbl[g];
#pragma unroll
        for (int h = 0; h < HH; h++) v += sA[h * SS + k] * sWl[h * HH + g];
        sP[idx] = v;
    }
    __syncthreads();

    // Row softmax over k (one warp per row, 8 warps cycling 12 rows)
    const int wid = tid >> 5, lane = tid & 31;
    for (int g = wid; g < HH; g += 8) {
        float* row = sP + g * SS;
        float m = -INFINITY;
        for (int k = lane; k < SS; k += 32) m = fmaxf(m, row[k]);
#pragma unroll
        for (int o = 16; o > 0; o >>= 1) m = fmaxf(m, __shfl_xor_sync(0xffffffffu, m, o));
        float s = 0.f;
        for (int k = lane; k < SS; k += 32) {
            float e = expf(row[k] - m);
            row[k] = e;
            s += e;
        }
#pragma unroll
        for (int o = 16; o > 0; o >>= 1) s += __shfl_xor_sync(0xffffffffu, s, o);
        float inv = 1.f / s;
        for (int k = lane; k < SS; k += 32) row[k] *= inv;
    }
    __syncthreads();

    // Post-softmax mix + writeback: out[g][k] = bw[g] + sum_h sP[h][k]*Ww[h][g]
    for (int idx = tid; idx < HH * SS; idx += 256) {
        int g = idx >> 10;
        int k = idx & 1023;
        float v = sbw[g];
#pragma unroll
        for (int h = 0; h < HH; h++) v += sP[h * SS + k] * sWw[h * HH + g];
        attn[((long long)(b * HH + g) << 20) + ((long long)q << 10) + k] = v;
    }
}

// ---------------------------------------------------------------------------
extern "C" void kernel_launch(void* const* d_in, const int* in_sizes, int n_in,
                              void* d_out, int out_size)
{
    const float* x     = (const float*)d_in[0];
    const float* Wqkv  = (const float*)d_in[1];
    const float* bqkv  = (const float*)d_in[2];
    const float* Wl    = (const float*)d_in[3];
    const float* bl    = (const float*)d_in[4];
    const float* Ww    = (const float*)d_in[5];
    const float* bw    = (const float*)d_in[6];
    const float* Wproj = (const float*)d_in[7];
    const float* bproj = (const float*)d_in[8];
    float* out = (float*)d_out;

    float *qkv_p, *attn_p, *obuf_p;
    cudaGetSymbolAddress((void**)&qkv_p, g_qkv);
    cudaGetSymbolAddress((void**)&attn_p, g_attn);
    cudaGetSymbolAddress((void**)&obuf_p, g_obuf);

    const int M = BB * SS;  // 4096

    // 1) QKV projection: [4096,768] @ [768,2304] + bqkv -> g_qkv
    {
        dim3 grid(D3 / 64, M / 128, 1);
        sgemm_k<false><<<grid, 256>>>(x, Wqkv, qkv_p, bqkv,
                                      M, D3, DD, DD, D3, D3, 1.0f,
                                      1, 0, 0, 0, 0, 0, 0);
    }

    // 2) Logits: per (b,h): scale * Q @ K^T -> g_attn [B,H,S,S]
    {
        dim3 grid(SS / 64, SS / 128, BB * HH);
        const float scale = 0.125f;  // 64^-0.5
        sgemm_k<true><<<grid, 256>>>(qkv_p /*Q at col 0*/, qkv_p + DD /*K*/, attn_p, nullptr,
                                     SS, SS, DH, D3, D3, SS, scale,
                                     HH,
                                     (long long)SS * D3, DH,          // A strides (b,h)
                                     (long long)SS * D3, DH,          // B strides (b,h)
                                     (long long)HH * SS * SS, (long long)SS * SS);
    }

    // 3) Fused pre-mix -> softmax -> post-mix (in place on g_attn)
    {
        size_t smem = (size_t)(2 * HH * SS + 2 * HH * HH + 2 * HH) * sizeof(float);
        cudaFuncSetAttribute(mix_softmax_k, cudaFuncAttributeMaxDynamicSharedMemorySize, (int)smem);
        mix_softmax_k<<<BB * SS, 256, smem>>>(attn_p, Wl, bl, Ww, bw);
    }

    // 4) AV: per (b,h): attn[S,S] @ V[S,dh] -> g_obuf[b,q,h,dh]
    {
        dim3 grid(DH / 64, SS / 128, BB * HH);
        sgemm_k<false><<<grid, 256>>>(attn_p, qkv_p + 2 * DD, obuf_p, nullptr,
                                      SS, DH, SS, SS, D3, DD, 1.0f,
                                      HH,
                                      (long long)HH * SS * SS, (long long)SS * SS,
                                      (long long)SS * D3, DH,
                                      (long long)SS * DD, DH);
    }

    // 5) Output projection: [4096,768] @ [768,768] + bproj -> d_out
    {
        dim3 grid(DD / 64, M / 128, 1);
        sgemm_k<false><<<grid, 256>>>(obuf_p, Wproj, out, bproj,
                                      M, DD, DD, DD, DD, DD, 1.0f,
                                      1, 0, 0, 0, 0, 0, 0);
    }
}

// round 4
// speedup vs baseline: 1.6485x; 1.6485x over previous
#include <cuda_runtime.h>
#include <cuda_bf16.h>
#include <math.h>
#include <stdint.h>

#define BB 4
#define SS 1024
#define DD 768
#define HH 12
#define DH 64
#define D3 2304

// ---------------- scratch (no runtime allocation allowed) ----------------
__device__ float g_qkv[(long long)BB * SS * D3];          // [B,S,3D] fp32
__device__ float g_attn[(long long)BB * HH * SS * SS];    // [B,H,S,S] fp32
__device__ float g_obuf[(long long)BB * SS * DD];         // [B,S,D] fp32
__device__ float g_wqkvT[(long long)D3 * DD];             // Wqkv^T [3D,D]
__device__ float g_wprojT[(long long)DD * DD];            // Wproj^T
__device__ float g_vT[(long long)BB * HH * DH * SS];      // V^T per (b,h): [dh,S]

__device__ __forceinline__ uint32_t smem_u32(const void* p) {
    uint32_t a;
    asm("{ .reg .u64 t; cvta.to.shared.u64 t, %1; cvt.u32.u64 %0, t; }" : "=r"(a) : "l"(p));
    return a;
}

__device__ __forceinline__ void ldsm_x4(uint32_t (&r)[4], uint32_t addr) {
    asm volatile("ldmatrix.sync.aligned.m8n8.x4.shared.b16 {%0,%1,%2,%3}, [%4];"
                 : "=r"(r[0]), "=r"(r[1]), "=r"(r[2]), "=r"(r[3]) : "r"(addr));
}
__device__ __forceinline__ void mma_bf16(float (&c)[4], const uint32_t (&a)[4],
                                         uint32_t b0, uint32_t b1) {
    asm volatile(
        "mma.sync.aligned.m16n8k16.row.col.f32.bf16.bf16.f32 "
        "{%0,%1,%2,%3}, {%4,%5,%6,%7}, {%8,%9}, {%0,%1,%2,%3};"
        : "+f"(c[0]), "+f"(c[1]), "+f"(c[2]), "+f"(c[3])
        : "r"(a[0]), "r"(a[1]), "r"(a[2]), "r"(a[3]), "r"(b0), "r"(b1));
}

// fp32 -> bf16 hi + lo split, 8B each to padded smem
__device__ __forceinline__ void split_store(char* hip, char* lop, float4 f) {
    __nv_bfloat162 h01 = __floats2bfloat162_rn(f.x, f.y);
    __nv_bfloat162 h23 = __floats2bfloat162_rn(f.z, f.w);
    float r0 = f.x - __bfloat162float(h01.x);
    float r1 = f.y - __bfloat162float(h01.y);
    float r2 = f.z - __bfloat162float(h23.x);
    float r3 = f.w - __bfloat162float(h23.y);
    __nv_bfloat162 l01 = __floats2bfloat162_rn(r0, r1);
    __nv_bfloat162 l23 = __floats2bfloat162_rn(r2, r3);
    uint2 uh, ul;
    uh.x = *(uint32_t*)&h01; uh.y = *(uint32_t*)&h23;
    ul.x = *(uint32_t*)&l01; ul.y = *(uint32_t*)&l23;
    *(uint2*)hip = uh;
    *(uint2*)lop = ul;
}

// smem layout (bytes), rows padded to 72 bf16 = 144B
#define OFF_A_HI 0
#define OFF_A_LO 18432
#define OFF_B_HI 36864
#define OFF_B_LO 46080
#define GEMM_SMEM 55296

// ---------------------------------------------------------------------------
// HMMA GEMM: C[128 x 64 tile] = alpha * A[M,K] @ B[N,K]^T + bias
// A row-major (lda), B row-major [N,K] (ldb). K % 64 == 0.
// bf16 hi/lo split (3 mma passes). Batched over z -> (b,h).
// ---------------------------------------------------------------------------
__global__ __launch_bounds__(256, 2)
void tc_gemm(const float* __restrict__ A, const float* __restrict__ B,
             float* __restrict__ C, const float* __restrict__ bias,
             int K, int lda, int ldb, int ldc, float alpha,
             int Hn, long long sAb, long long sAh, long long sBb, long long sBh,
             long long sCb, long long sCh)
{
    extern __shared__ char smem[];
    const uint32_t sb = smem_u32(smem);
    const int tid = threadIdx.x, wid = tid >> 5, lane = tid & 31;

    const int z = blockIdx.z;
    const int b = z / Hn, h = z % Hn;
    A += b * sAb + h * sAh;
    B += b * sBb + h * sBh;
    C += b * sCb + h * sCh;
    const int m0 = blockIdx.y << 7;
    const int n0 = blockIdx.x << 6;

    const int wm = wid >> 1;          // 0..3 -> 32-row slab
    const int wn = wid & 1;           // 0..1 -> 32-col slab

    float acc[2][4][4];
#pragma unroll
    for (int i = 0; i < 2; i++)
#pragma unroll
        for (int j = 0; j < 4; j++)
#pragma unroll
            for (int t = 0; t < 4; t++) acc[i][j][t] = 0.f;

    // ldmatrix lane base addresses (k offsets added per chunk)
    const uint32_t aRow = (uint32_t)(wm * 32 + (lane & 15));
    const uint32_t aCol = (uint32_t)(((lane >> 4) & 1) * 8);
    // B (non-trans): octet0 n0-7/k0, octet1 n0-7/k8, octet2 n8-15/k0, octet3 n8-15/k8
    const uint32_t bRowBase = (uint32_t)(wn * 32 + (lane & 7) + ((lane >> 4) & 1) * 8);
    const uint32_t bCol = (uint32_t)(((lane >> 3) & 1) * 8);

    for (int kt = 0; kt < K; kt += 64) {
        // A tile: 128 x 64 fp32 (2048 float4), 8 per thread
#pragma unroll
        for (int i = 0; i < 8; i++) {
            int idx = tid + (i << 8);
            int row = idx >> 4, c4 = idx & 15;
            float4 f = *reinterpret_cast<const float4*>(A + (long long)(m0 + row) * lda + kt + (c4 << 2));
            uint32_t off = row * 144 + (c4 << 3);
            split_store(smem + OFF_A_HI + off, smem + OFF_A_LO + off, f);
        }
        // B tile: 64 x 64 fp32 (1024 float4), 4 per thread
#pragma unroll
        for (int i = 0; i < 4; i++) {
            int idx = tid + (i << 8);
            int row = idx >> 4, c4 = idx & 15;
            float4 f = *reinterpret_cast<const float4*>(B + (long long)(n0 + row) * ldb + kt + (c4 << 2));
            uint32_t off = row * 144 + (c4 << 3);
            split_store(smem + OFF_B_HI + off, smem + OFF_B_LO + off, f);
        }
        __syncthreads();

#pragma unroll
        for (int kc = 0; kc < 4; kc++) {
            const uint32_t ak = (uint32_t)(kc * 16) + aCol;
            const uint32_t bk = (uint32_t)(kc * 16) + bCol;
            uint32_t Ah[2][4], Al[2][4], Bh[2][4], Bl[2][4];
#pragma unroll
            for (int mt = 0; mt < 2; mt++) {
                uint32_t ad = sb + (aRow + mt * 16) * 144 + ak * 2;
                ldsm_x4(Ah[mt], ad + OFF_A_HI);
                ldsm_x4(Al[mt], ad + OFF_A_LO);
            }
#pragma unroll
            for (int nb = 0; nb < 2; nb++) {
                uint32_t bd = sb + (bRowBase + nb * 16) * 144 + bk * 2;
                ldsm_x4(Bh[nb], bd + OFF_B_HI);
                ldsm_x4(Bl[nb], bd + OFF_B_LO);
            }
#pragma unroll
            for (int mt = 0; mt < 2; mt++)
#pragma unroll
                for (int nt = 0; nt < 4; nt++) {
                    const int nb = nt >> 1, sub = (nt & 1) * 2;
                    mma_bf16(acc[mt][nt], Ah[mt], Bh[nb][sub], Bh[nb][sub + 1]);
                    mma_bf16(acc[mt][nt], Ah[mt], Bl[nb][sub], Bl[nb][sub + 1]);
                    mma_bf16(acc[mt][nt], Al[mt], Bh[nb][sub], Bh[nb][sub + 1]);
                }
        }
        __syncthreads();
    }

    // epilogue
    const int g = lane >> 2, tig = lane & 3;
#pragma unroll
    for (int mt = 0; mt < 2; mt++) {
        const int row = m0 + wm * 32 + mt * 16 + g;
#pragma unroll
        for (int nt = 0; nt < 4; nt++) {
            const int col = n0 + wn * 32 + nt * 8 + tig * 2;
            float2 v0, v1;
            v0.x = alpha * acc[mt][nt][0];
            v0.y = alpha * acc[mt][nt][1];
            v1.x = alpha * acc[mt][nt][2];
            v1.y = alpha * acc[mt][nt][3];
            if (bias) {
                float2 bv = *reinterpret_cast<const float2*>(bias + col);
                v0.x += bv.x; v0.y += bv.y;
                v1.x += bv.x; v1.y += bv.y;
            }
            *reinterpret_cast<float2*>(C + (long long)row * ldc + col) = v0;
            *reinterpret_cast<float2*>(C + (long long)(row + 8) * ldc + col) = v1;
        }
    }
}

// ---------------------------------------------------------------------------
// batched 32x32 tiled transpose
// ---------------------------------------------------------------------------
__global__ __launch_bounds__(256)
void transpose_k(const float* __restrict__ in, float* __restrict__ out,
                 int ldi, int ldo, int Hn,
                 long long siB, long long siH, long long soB, long long soH)
{
    __shared__ float t[32][33];
    const int z = blockIdx.z, b = z / Hn, h = z % Hn;
    in += b * siB + h * siH;
    out += b * soB + h * soH;
    const int r0 = blockIdx.y << 5, c0 = blockIdx.x << 5;
    const int tx = threadIdx.x, ty = threadIdx.y;
#pragma unroll
    for (int i = ty; i < 32; i += 8)
        t[i][tx] = in[(long long)(r0 + i) * ldi + c0 + tx];
    __syncthreads();
#pragma unroll
    for (int i = ty; i < 32; i += 8)
        out[(long long)(c0 + i) * ldo + r0 + tx] = t[tx][i];
}

// ---------------------------------------------------------------------------
// Fused talking-heads: pre-mix -> softmax -> post-mix, in place on g_attn.
// One block per (b,q).
// ---------------------------------------------------------------------------
__global__ __launch_bounds__(256, 4)
void mix_softmax_k(float* __restrict__ attn,
                   const float* __restrict__ Wl, const float* __restrict__ bl,
                   const float* __restrict__ Ww, const float* __restrict__ bw)
{
    extern __shared__ float sm[];
    float* sP  = sm;                    // 12*1024
    float* sWl = sP + HH * SS;
    float* sWw = sWl + HH * HH;
    float* sbl = sWw + HH * HH;
    float* sbw = sbl + HH;

    const int blk = blockIdx.x;
    const int b = blk >> 10, q = blk & 1023;
    const int tid = threadIdx.x;

    for (int i = tid; i < HH * HH; i += 256) { sWl[i] = Wl[i]; sWw[i] = Ww[i]; }
    if (tid < HH) { sbl[tid] = bl[tid]; sbw[tid] = bw[tid]; }
    __syncthreads();

    const long long base = (((long long)b * HH) << 20) + ((long long)q << 10);

    for (int k = tid; k < SS; k += 256) {
        float a[HH];
#pragma unroll
        for (int hh = 0; hh < HH; hh++) a[hh] = attn[base + ((long long)hh << 20) + k];
#pragma unroll
        for (int g = 0; g < HH; g++) {
            float v = sbl[g];
#pragma unroll
            for (int hh = 0; hh < HH; hh++) v = fmaf(a[hh], sWl[hh * HH + g], v);
            sP[g * SS + k] = v;
        }
    }
    __syncthreads();

    const int wid = tid >> 5, lane = tid & 31;
    for (int g = wid; g < HH; g += 8) {
        float* row = sP + g * SS;
        float m = -1e30f;
        for (int k = lane; k < SS; k += 32) m = fmaxf(m, row[k]);
#pragma unroll
        for (int o = 16; o; o >>= 1) m = fmaxf(m, __shfl_xor_sync(0xffffffffu, m, o));
        float s = 0.f;
        for (int k = lane; k < SS; k += 32) {
            float e = __expf(row[k] - m);
            row[k] = e;
            s += e;
        }
#pragma unroll
        for (int o = 16; o; o >>= 1) s += __shfl_xor_sync(0xffffffffu, s, o);
        float inv = 1.f / s;
        for (int k = lane; k < SS; k += 32) row[k] *= inv;
    }
    __syncthreads();

    for (int k = tid; k < SS; k += 256) {
        float p[HH];
#pragma unroll
        for (int hh = 0; hh < HH; hh++) p[hh] = sP[hh * SS + k];
#pragma unroll
        for (int g = 0; g < HH; g++) {
            float v = sbw[g];
#pragma unroll
            for (int hh = 0; hh < HH; hh++) v = fmaf(p[hh], sWw[hh * HH + g], v);
            attn[base + ((long long)g << 20) + k] = v;
        }
    }
}

// ---------------------------------------------------------------------------
extern "C" void kernel_launch(void* const* d_in, const int* in_sizes, int n_in,
                              void* d_out, int out_size)
{
    const float* x     = (const float*)d_in[0];
    const float* Wqkv  = (const float*)d_in[1];
    const float* bqkv  = (const float*)d_in[2];
    const float* Wl    = (const float*)d_in[3];
    const float* bl    = (const float*)d_in[4];
    const float* Ww    = (const float*)d_in[5];
    const float* bw    = (const float*)d_in[6];
    const float* Wproj = (const float*)d_in[7];
    const float* bproj = (const float*)d_in[8];
    float* out = (float*)d_out;

    float *qkv_p, *attn_p, *obuf_p, *wqkvT_p, *wprojT_p, *vT_p;
    cudaGetSymbolAddress((void**)&qkv_p, g_qkv);
    cudaGetSymbolAddress((void**)&attn_p, g_attn);
    cudaGetSymbolAddress((void**)&obuf_p, g_obuf);
    cudaGetSymbolAddress((void**)&wqkvT_p, g_wqkvT);
    cudaGetSymbolAddress((void**)&wprojT_p, g_wprojT);
    cudaGetSymbolAddress((void**)&vT_p, g_vT);

    cudaFuncSetAttribute(tc_gemm, cudaFuncAttributeMaxDynamicSharedMemorySize, GEMM_SMEM);
    const size_t mix_smem = (HH * SS + 2 * HH * HH + 2 * HH) * sizeof(float);
    cudaFuncSetAttribute(mix_softmax_k, cudaFuncAttributeMaxDynamicSharedMemorySize, (int)mix_smem);

    // 0) weight transposes
    transpose_k<<<dim3(D3 / 32, DD / 32, 1), dim3(32, 8)>>>(
        Wqkv, wqkvT_p, D3, DD, 1, 0, 0, 0, 0);
    transpose_k<<<dim3(DD / 32, DD / 32, 1), dim3(32, 8)>>>(
        Wproj, wprojT_p, DD, DD, 1, 0, 0, 0, 0);

    // 1) QKV: [4096,768] @ WqkvT[2304,768]^T + bqkv -> g_qkv
    tc_gemm<<<dim3(D3 / 64, 32, 1), 256, GEMM_SMEM>>>(
        x, wqkvT_p, qkv_p, bqkv,
        DD, DD, DD, D3, 1.0f,
        1, 0, 0, 0, 0, 0, 0);

    // 2) V transpose: qkv[b,s,1536+h*64+d] -> vT[(b,h),d,s]
    transpose_k<<<dim3(DH / 32, SS / 32, BB * HH), dim3(32, 8)>>>(
        qkv_p + 2 * DD, vT_p, D3, SS, HH,
        (long long)SS * D3, 64,
        (long long)HH * DH * SS, (long long)DH * SS);

    // 3) logits: 0.125 * Q @ K^T -> g_attn
    tc_gemm<<<dim3(SS / 64, SS / 128, BB * HH), 256, GEMM_SMEM>>>(
        qkv_p, qkv_p + DD, attn_p, nullptr,
        DH, D3, D3, SS, 0.125f,
        HH,
        (long long)SS * D3, 64,
        (long long)SS * D3, 64,
        (long long)HH * SS * SS, (long long)SS * SS);

    // 4) pre-mix -> softmax -> post-mix (in place)
    mix_softmax_k<<<BB * SS, 256, mix_smem>>>(attn_p, Wl, bl, Ww, bw);

    // 5) AV: attn @ vT^T -> obuf[b,q,h,:]
    tc_gemm<<<dim3(1, SS / 128, BB * HH), 256, GEMM_SMEM>>>(
        attn_p, vT_p, obuf_p, nullptr,
        SS, SS, SS, DD, 1.0f,
        HH,
        (long long)HH * SS * SS, (long long)SS * SS,
        (long long)HH * DH * SS, (long long)DH * SS,
        (long long)SS * DD, 64);

    // 6) proj + bproj -> out
    tc_gemm<<<dim3(DD / 64, 32, 1), 256, GEMM_SMEM>>>(
        obuf_p, wprojT_p, out, bproj,
        DD, DD, DD, DD, 1.0f,
        1, 0, 0, 0, 0, 0, 0);
}

// round 5
// speedup vs baseline: 2.0000x; 1.2132x over previous
#include <cuda_runtime.h>
#include <cuda_bf16.h>
#include <math.h>
#include <stdint.h>

#define BB 4
#define SS 1024
#define DD 768
#define HH 12
#define DH 64
#define D3 2304

typedef __nv_bfloat16 bf16;

// ---------------- scratch (no runtime allocation) ----------------
__device__ bf16 g_xh[(long long)BB * SS * DD], g_xl[(long long)BB * SS * DD];
__device__ bf16 g_wqkvTh[(long long)D3 * DD], g_wqkvTl[(long long)D3 * DD];
__device__ bf16 g_wprojTh[(long long)DD * DD], g_wprojTl[(long long)DD * DD];
__device__ bf16 g_qkvh[(long long)BB * SS * D3], g_qkvl[(long long)BB * SS * D3];
__device__ bf16 g_vTh[(long long)BB * HH * DH * SS], g_vTl[(long long)BB * HH * DH * SS];
__device__ float g_attn[(long long)BB * HH * SS * SS];
__device__ bf16 g_attnh[(long long)BB * HH * SS * SS], g_attnl[(long long)BB * HH * SS * SS];
__device__ bf16 g_obufh[(long long)BB * SS * DD], g_obufl[(long long)BB * SS * DD];

// ---------------- helpers ----------------
__device__ __forceinline__ uint32_t smem_u32(const void* p) {
    uint32_t a;
    asm("{ .reg .u64 t; cvta.to.shared.u64 t, %1; cvt.u32.u64 %0, t; }" : "=r"(a) : "l"(p));
    return a;
}
__device__ __forceinline__ void cp16(uint32_t dst, const void* src) {
    asm volatile("cp.async.cg.shared.global [%0], [%1], 16;" :: "r"(dst), "l"(src));
}
#define CP_COMMIT() asm volatile("cp.async.commit_group;" ::: "memory")
#define CP_WAIT(n)  asm volatile("cp.async.wait_group %0;" :: "n"(n) : "memory")

__device__ __forceinline__ void ldsm_x4(uint32_t (&r)[4], uint32_t addr) {
    asm volatile("ldmatrix.sync.aligned.m8n8.x4.shared.b16 {%0,%1,%2,%3}, [%4];"
                 : "=r"(r[0]), "=r"(r[1]), "=r"(r[2]), "=r"(r[3]) : "r"(addr));
}
__device__ __forceinline__ void mma_bf16(float (&c)[4], const uint32_t (&a)[4],
                                         uint32_t b0, uint32_t b1) {
    asm volatile(
        "mma.sync.aligned.m16n8k16.row.col.f32.bf16.bf16.f32 "
        "{%0,%1,%2,%3}, {%4,%5,%6,%7}, {%8,%9}, {%0,%1,%2,%3};"
        : "+f"(c[0]), "+f"(c[1]), "+f"(c[2]), "+f"(c[3])
        : "r"(a[0]), "r"(a[1]), "r"(a[2]), "r"(a[3]), "r"(b0), "r"(b1));
}
// fp32x2 -> packed bf16x2 hi + lo residual
__device__ __forceinline__ uint32_t split2(float x, float y, uint32_t& lo) {
    __nv_bfloat162 h = __floats2bfloat162_rn(x, y);
    __nv_bfloat162 l = __floats2bfloat162_rn(x - __bfloat162float(h.x),
                                             y - __bfloat162float(h.y));
    lo = *(uint32_t*)&l;
    return *(uint32_t*)&h;
}
__device__ __forceinline__ uint32_t sw128(uint32_t off) { return off ^ ((off >> 3) & 0x70); }

// smem stage layout (bytes): A_hi 16K | A_lo 16K | B_hi 8K | B_lo 8K
#define OFF_AH 0
#define OFF_AL 16384
#define OFF_BH 32768
#define OFF_BL 40960
#define STAGE  49152
#define GEMM_SMEM (2 * STAGE)

// ---------------------------------------------------------------------------
// Double-buffered bf16 HMMA GEMM: C[128x64] = alpha*A@B^T + bias
// A = Ah+Al [M,K] row-major bf16 pairs, B = Bh+Bl [N,K] row-major bf16 pairs.
// Output: fp32 (Cf) or bf16 hi/lo (Ch/Cl). K % 64 == 0. Batched over z->(b,h).
// ---------------------------------------------------------------------------
__device__ __forceinline__ void load_stage(
    uint32_t sbase, const bf16* Ah, const bf16* Al, const bf16* Bh, const bf16* Bl,
    int lda, int ldb, int m0, int n0, int kbase, int tid)
{
#pragma unroll
    for (int i = 0; i < 4; i++) {
        int c = tid + (i << 8);
        int row = c >> 3, c16 = c & 7;
        uint32_t sw = sw128((row << 7) + (c16 << 4));
        long long src = (long long)(m0 + row) * lda + kbase + (c16 << 3);
        cp16(sbase + OFF_AH + sw, Ah + src);
        cp16(sbase + OFF_AL + sw, Al + src);
    }
#pragma unroll
    for (int i = 0; i < 2; i++) {
        int c = tid + (i << 8);
        int row = c >> 3, c16 = c & 7;
        uint32_t sw = sw128((row << 7) + (c16 << 4));
        long long src = (long long)(n0 + row) * ldb + kbase + (c16 << 3);
        cp16(sbase + OFF_BH + sw, Bh + src);
        cp16(sbase + OFF_BL + sw, Bl + src);
    }
}

__global__ __launch_bounds__(256)
void tc_gemm2(const bf16* __restrict__ Ah, const bf16* __restrict__ Al,
              const bf16* __restrict__ Bh, const bf16* __restrict__ Bl,
              float* __restrict__ Cf, bf16* __restrict__ Ch, bf16* __restrict__ Cl,
              const float* __restrict__ bias,
              int K, int lda, int ldb, int ldc, float alpha, int Hn,
              long long sAb, long long sAh, long long sBb, long long sBh,
              long long sCb, long long sChh)
{
    extern __shared__ char smem[];
    const uint32_t sb = smem_u32(smem);
    const int tid = threadIdx.x, wid = tid >> 5, lane = tid & 31;

    const int z = blockIdx.z;
    const int b = z / Hn, h = z % Hn;
    Ah += b * sAb + h * sAh;  Al += b * sAb + h * sAh;
    Bh += b * sBb + h * sBh;  Bl += b * sBb + h * sBh;
    const long long coff = b * sCb + h * sChh;
    const int m0 = blockIdx.y << 7;
    const int n0 = blockIdx.x << 6;

    const int wm = wid >> 1, wn = wid & 1;

    float acc[2][4][4];
#pragma unroll
    for (int i = 0; i < 2; i++)
#pragma unroll
        for (int j = 0; j < 4; j++)
#pragma unroll
            for (int t = 0; t < 4; t++) acc[i][j][t] = 0.f;

    const uint32_t aRow = (uint32_t)(wm * 32 + (lane & 15));
    const uint32_t aSel = (uint32_t)(((lane >> 4) & 1) * 16);   // byte offset within k16
    const uint32_t bRow = (uint32_t)(wn * 32 + (lane & 7) + ((lane >> 4) & 1) * 8);
    const uint32_t bSel = (uint32_t)(((lane >> 3) & 1) * 16);

    const int nst = K >> 6;
    load_stage(sb, Ah, Al, Bh, Bl, lda, ldb, m0, n0, 0, tid);
    CP_COMMIT();

    for (int s = 0; s < nst; s++) {
        if (s + 1 < nst) {
            load_stage(sb + ((s + 1) & 1) * STAGE, Ah, Al, Bh, Bl, lda, ldb, m0, n0, (s + 1) << 6, tid);
            CP_COMMIT();
            CP_WAIT(1);
        } else {
            CP_WAIT(0);
        }
        __syncthreads();

        const uint32_t st = sb + (s & 1) * STAGE;
#pragma unroll
        for (int kc = 0; kc < 4; kc++) {
            const uint32_t akb = (uint32_t)(kc * 32) + aSel;
            const uint32_t bkb = (uint32_t)(kc * 32) + bSel;
            uint32_t Ahf[2][4], Alf[2][4], Bhf[2][4], Blf[2][4];
#pragma unroll
            for (int mt = 0; mt < 2; mt++) {
                uint32_t sw = sw128(((aRow + mt * 16) << 7) + akb);
                ldsm_x4(Ahf[mt], st + OFF_AH + sw);
                ldsm_x4(Alf[mt], st + OFF_AL + sw);
            }
#pragma unroll
            for (int nb = 0; nb < 2; nb++) {
                uint32_t sw = sw128(((bRow + nb * 16) << 7) + bkb);
                ldsm_x4(Bhf[nb], st + OFF_BH + sw);
                ldsm_x4(Blf[nb], st + OFF_BL + sw);
            }
#pragma unroll
            for (int mt = 0; mt < 2; mt++)
#pragma unroll
                for (int nt = 0; nt < 4; nt++) {
                    const int nb = nt >> 1, sub = (nt & 1) * 2;
                    mma_bf16(acc[mt][nt], Ahf[mt], Bhf[nb][sub], Bhf[nb][sub + 1]);
                    mma_bf16(acc[mt][nt], Ahf[mt], Blf[nb][sub], Blf[nb][sub + 1]);
                    mma_bf16(acc[mt][nt], Alf[mt], Bhf[nb][sub], Bhf[nb][sub + 1]);
                }
        }
        __syncthreads();
    }

    // epilogue
    const int g = lane >> 2, tig = lane & 3;
#pragma unroll
    for (int mt = 0; mt < 2; mt++) {
        const int row = m0 + wm * 32 + mt * 16 + g;
#pragma unroll
        for (int nt = 0; nt < 4; nt++) {
            const int col = n0 + wn * 32 + nt * 8 + tig * 2;
            float vx0 = alpha * acc[mt][nt][0], vy0 = alpha * acc[mt][nt][1];
            float vx1 = alpha * acc[mt][nt][2], vy1 = alpha * acc[mt][nt][3];
            if (bias) {
                float2 bv = *reinterpret_cast<const float2*>(bias + col);
                vx0 += bv.x; vy0 += bv.y; vx1 += bv.x; vy1 += bv.y;
            }
            const long long i0 = coff + (long long)row * ldc + col;
            const long long i1 = coff + (long long)(row + 8) * ldc + col;
            if (Cf) {
                *reinterpret_cast<float2*>(Cf + i0) = make_float2(vx0, vy0);
                *reinterpret_cast<float2*>(Cf + i1) = make_float2(vx1, vy1);
            } else {
                uint32_t lo0, lo1;
                uint32_t hi0 = split2(vx0, vy0, lo0);
                uint32_t hi1 = split2(vx1, vy1, lo1);
                *reinterpret_cast<uint32_t*>(Ch + i0) = hi0;
                *reinterpret_cast<uint32_t*>(Cl + i0) = lo0;
                *reinterpret_cast<uint32_t*>(Ch + i1) = hi1;
                *reinterpret_cast<uint32_t*>(Cl + i1) = lo1;
            }
        }
    }
}

// ---------------------------------------------------------------------------
// elementwise fp32 -> bf16 hi/lo split
// ---------------------------------------------------------------------------
__global__ __launch_bounds__(256)
void split_k(const float* __restrict__ in, bf16* __restrict__ oh, bf16* __restrict__ ol, int n4)
{
    int i = blockIdx.x * 256 + threadIdx.x;
    if (i >= n4) return;
    float4 f = reinterpret_cast<const float4*>(in)[i];
    uint32_t lo0, lo1;
    uint32_t hi0 = split2(f.x, f.y, lo0);
    uint32_t hi1 = split2(f.z, f.w, lo1);
    reinterpret_cast<uint2*>(oh)[i] = make_uint2(hi0, hi1);
    reinterpret_cast<uint2*>(ol)[i] = make_uint2(lo0, lo1);
}

// ---------------------------------------------------------------------------
// transpose fp32 [R,C] -> bf16 hi/lo [C,R]
// ---------------------------------------------------------------------------
__global__ __launch_bounds__(256)
void transpose_split_k(const float* __restrict__ in, bf16* __restrict__ oh,
                       bf16* __restrict__ ol, int ldi, int ldo)
{
    __shared__ float t[32][33];
    const int r0 = blockIdx.y << 5, c0 = blockIdx.x << 5;
    const int tx = threadIdx.x, ty = threadIdx.y;
#pragma unroll
    for (int i = ty; i < 32; i += 8)
        t[i][tx] = in[(long long)(r0 + i) * ldi + c0 + tx];
    __syncthreads();
#pragma unroll
    for (int i = ty; i < 32; i += 8) {
        float v = t[tx][i];
        bf16 hv = __float2bfloat16(v);
        bf16 lv = __float2bfloat16(v - __bfloat162float(hv));
        long long o = (long long)(c0 + i) * ldo + r0 + tx;
        oh[o] = hv;
        ol[o] = lv;
    }
}

// ---------------------------------------------------------------------------
// batched pair transpose bf16: vT[(b,h),d,s] from qkv hi/lo V block
// ---------------------------------------------------------------------------
__global__ __launch_bounds__(256)
void transpose_pair_k(const bf16* __restrict__ inh, const bf16* __restrict__ inl,
                      bf16* __restrict__ oh, bf16* __restrict__ ol,
                      int ldi, int ldo, int Hn,
                      long long siB, long long siH, long long soB, long long soH)
{
    __shared__ bf16 th[32][33], tl[32][33];
    const int z = blockIdx.z, b = z / Hn, h = z % Hn;
    inh += b * siB + h * siH;  inl += b * siB + h * siH;
    oh  += b * soB + h * soH;  ol  += b * soB + h * soH;
    const int r0 = blockIdx.y << 5, c0 = blockIdx.x << 5;
    const int tx = threadIdx.x, ty = threadIdx.y;
#pragma unroll
    for (int i = ty; i < 32; i += 8) {
        long long s = (long long)(r0 + i) * ldi + c0 + tx;
        th[i][tx] = inh[s];
        tl[i][tx] = inl[s];
    }
    __syncthreads();
#pragma unroll
    for (int i = ty; i < 32; i += 8) {
        long long o = (long long)(c0 + i) * ldo + r0 + tx;
        oh[o] = th[tx][i];
        ol[o] = tl[tx][i];
    }
}

// ---------------------------------------------------------------------------
// Fused talking-heads: pre-mix -> softmax -> post-mix; reads fp32, writes hi/lo
// ---------------------------------------------------------------------------
__global__ __launch_bounds__(256, 4)
void mix_softmax_k(const float* __restrict__ attn,
                   bf16* __restrict__ ah, bf16* __restrict__ al,
                   const float* __restrict__ Wl, const float* __restrict__ bl,
                   const float* __restrict__ Ww, const float* __restrict__ bw)
{
    extern __shared__ float sm[];
    float* sP  = sm;                    // 12*1024
    float* sWl = sP + HH * SS;
    float* sWw = sWl + HH * HH;
    float* sbl = sWw + HH * HH;
    float* sbw = sbl + HH;

    const int blk = blockIdx.x;
    const int b = blk >> 10, q = blk & 1023;
    const int tid = threadIdx.x;

    for (int i = tid; i < HH * HH; i += 256) { sWl[i] = Wl[i]; sWw[i] = Ww[i]; }
    if (tid < HH) { sbl[tid] = bl[tid]; sbw[tid] = bw[tid]; }
    __syncthreads();

    const long long base = (((long long)b * HH) << 20) + ((long long)q << 10);

    for (int k = tid; k < SS; k += 256) {
        float a[HH];
#pragma unroll
        for (int hh = 0; hh < HH; hh++) a[hh] = attn[base + ((long long)hh << 20) + k];
#pragma unroll
        for (int g = 0; g < HH; g++) {
            float v = sbl[g];
#pragma unroll
            for (int hh = 0; hh < HH; hh++) v = fmaf(a[hh], sWl[hh * HH + g], v);
            sP[g * SS + k] = v;
        }
    }
    __syncthreads();

    const int wid = tid >> 5, lane = tid & 31;
    for (int g = wid; g < HH; g += 8) {
        float* row = sP + g * SS;
        float m = -1e30f;
        for (int k = lane; k < SS; k += 32) m = fmaxf(m, row[k]);
#pragma unroll
        for (int o = 16; o; o >>= 1) m = fmaxf(m, __shfl_xor_sync(0xffffffffu, m, o));
        float s = 0.f;
        for (int k = lane; k < SS; k += 32) {
            float e = __expf(row[k] - m);
            row[k] = e;
            s += e;
        }
#pragma unroll
        for (int o = 16; o; o >>= 1) s += __shfl_xor_sync(0xffffffffu, s, o);
        float inv = 1.f / s;
        for (int k = lane; k < SS; k += 32) row[k] *= inv;
    }
    __syncthreads();

    for (int k = tid; k < SS; k += 256) {
        float p[HH];
#pragma unroll
        for (int hh = 0; hh < HH; hh++) p[hh] = sP[hh * SS + k];
#pragma unroll
        for (int g = 0; g < HH; g++) {
            float v = sbw[g];
#pragma unroll
            for (int hh = 0; hh < HH; hh++) v = fmaf(p[hh], sWw[hh * HH + g], v);
            bf16 hv = __float2bfloat16(v);
            bf16 lv = __float2bfloat16(v - __bfloat162float(hv));
            long long o = base + ((long long)g << 20) + k;
            ah[o] = hv;
            al[o] = lv;
        }
    }
}

// ---------------------------------------------------------------------------
extern "C" void kernel_launch(void* const* d_in, const int* in_sizes, int n_in,
                              void* d_out, int out_size)
{
    const float* x     = (const float*)d_in[0];
    const float* Wqkv  = (const float*)d_in[1];
    const float* bqkv  = (const float*)d_in[2];
    const float* Wl    = (const float*)d_in[3];
    const float* bl    = (const float*)d_in[4];
    const float* Ww    = (const float*)d_in[5];
    const float* bw    = (const float*)d_in[6];
    const float* Wproj = (const float*)d_in[7];
    const float* bproj = (const float*)d_in[8];
    float* out = (float*)d_out;

    bf16 *xh, *xl, *wqh, *wql, *wph, *wpl, *qh, *ql, *vth, *vtl, *ath, *atl, *obh, *obl;
    float* attn;
    cudaGetSymbolAddress((void**)&xh, g_xh);     cudaGetSymbolAddress((void**)&xl, g_xl);
    cudaGetSymbolAddress((void**)&wqh, g_wqkvTh); cudaGetSymbolAddress((void**)&wql, g_wqkvTl);
    cudaGetSymbolAddress((void**)&wph, g_wprojTh); cudaGetSymbolAddress((void**)&wpl, g_wprojTl);
    cudaGetSymbolAddress((void**)&qh, g_qkvh);   cudaGetSymbolAddress((void**)&ql, g_qkvl);
    cudaGetSymbolAddress((void**)&vth, g_vTh);   cudaGetSymbolAddress((void**)&vtl, g_vTl);
    cudaGetSymbolAddress((void**)&attn, g_attn);
    cudaGetSymbolAddress((void**)&ath, g_attnh); cudaGetSymbolAddress((void**)&atl, g_attnl);
    cudaGetSymbolAddress((void**)&obh, g_obufh); cudaGetSymbolAddress((void**)&obl, g_obufl);

    cudaFuncSetAttribute(tc_gemm2, cudaFuncAttributeMaxDynamicSharedMemorySize, GEMM_SMEM);
    const size_t mix_smem = (HH * SS + 2 * HH * HH + 2 * HH) * sizeof(float);
    cudaFuncSetAttribute(mix_softmax_k, cudaFuncAttributeMaxDynamicSharedMemorySize, (int)mix_smem);

    // 0) operand prep
    split_k<<<(BB * SS * DD / 4 + 255) / 256, 256>>>(x, xh, xl, BB * SS * DD / 4);
    transpose_split_k<<<dim3(D3 / 32, DD / 32), dim3(32, 8)>>>(Wqkv, wqh, wql, D3, DD);
    transpose_split_k<<<dim3(DD / 32, DD / 32), dim3(32, 8)>>>(Wproj, wph, wpl, DD, DD);

    // 1) QKV: x @ WqkvT^T + bqkv -> qkv hi/lo
    tc_gemm2<<<dim3(D3 / 64, 32, 1), 256, GEMM_SMEM>>>(
        xh, xl, wqh, wql, nullptr, qh, ql, bqkv,
        DD, DD, DD, D3, 1.0f, 1, 0, 0, 0, 0, 0, 0);

    // 2) V transpose: qkv[...,1536+h*64+d] -> vT[(b,h),d,s]
    transpose_pair_k<<<dim3(DH / 32, SS / 32, BB * HH), dim3(32, 8)>>>(
        qh + 2 * DD, ql + 2 * DD, vth, vtl, D3, SS, HH,
        (long long)SS * D3, 64,
        (long long)HH * DH * SS, (long long)DH * SS);

    // 3) logits: 0.125 * Q @ K^T -> attn fp32
    tc_gemm2<<<dim3(SS / 64, SS / 128, BB * HH), 256, GEMM_SMEM>>>(
        qh, ql, qh + DD, ql + DD, attn, nullptr, nullptr, nullptr,
        DH, D3, D3, SS, 0.125f, HH,
        (long long)SS * D3, 64,
        (long long)SS * D3, 64,
        (long long)HH * SS * SS, (long long)SS * SS);

    // 4) pre-mix -> softmax -> post-mix -> attn hi/lo
    mix_softmax_k<<<BB * SS, 256, mix_smem>>>(attn, ath, atl, Wl, bl, Ww, bw);

    // 5) AV: attn @ vT^T -> obuf hi/lo [b,q,h*64+d]
    tc_gemm2<<<dim3(1, SS / 128, BB * HH), 256, GEMM_SMEM>>>(
        ath, atl, vth, vtl, nullptr, obh, obl, nullptr,
        SS, SS, SS, DD, 1.0f, HH,
        (long long)HH * SS * SS, (long long)SS * SS,
        (long long)HH * DH * SS, (long long)DH * SS,
        (long long)SS * DD, 64);

    // 6) proj: obuf @ WprojT^T + bproj -> out fp32
    tc_gemm2<<<dim3(DD / 64, 32, 1), 256, GEMM_SMEM>>>(
        obh, obl, wph, wpl, out, nullptr, nullptr, bproj,
        DD, DD, DD, DD, 1.0f, 1, 0, 0, 0, 0, 0, 0);
}

// round 6
// speedup vs baseline: 2.0272x; 1.0136x over previous
#include <cuda_runtime.h>
#include <cuda_bf16.h>
#include <math.h>
#include <stdint.h>

#define BB 4
#define SS 1024
#define DD 768
#define HH 12
#define DH 64
#define D3 2304

typedef __nv_bfloat16 bf16;

// ---------------- scratch (no runtime allocation) ----------------
__device__ bf16 g_xh[(long long)BB * SS * DD], g_xl[(long long)BB * SS * DD];
__device__ bf16 g_wqkvTh[(long long)D3 * DD], g_wqkvTl[(long long)D3 * DD];
__device__ bf16 g_wprojTh[(long long)DD * DD], g_wprojTl[(long long)DD * DD];
__device__ bf16 g_qkvh[(long long)BB * SS * D3], g_qkvl[(long long)BB * SS * D3];
__device__ bf16 g_vTh[(long long)BB * HH * DH * SS], g_vTl[(long long)BB * HH * DH * SS];
__device__ float g_attn[(long long)BB * HH * SS * SS];
__device__ bf16 g_attnh[(long long)BB * HH * SS * SS], g_attnl[(long long)BB * HH * SS * SS];
__device__ bf16 g_obufh[(long long)BB * SS * DD], g_obufl[(long long)BB * SS * DD];

// ---------------- helpers ----------------
__device__ __forceinline__ uint32_t smem_u32(const void* p) {
    uint32_t a;
    asm("{ .reg .u64 t; cvta.to.shared.u64 t, %1; cvt.u32.u64 %0, t; }" : "=r"(a) : "l"(p));
    return a;
}
__device__ __forceinline__ void cp16(uint32_t dst, const void* src) {
    asm volatile("cp.async.cg.shared.global [%0], [%1], 16;" :: "r"(dst), "l"(src));
}
#define CP_COMMIT() asm volatile("cp.async.commit_group;" ::: "memory")
#define CP_WAIT(n)  asm volatile("cp.async.wait_group %0;" :: "n"(n) : "memory")

__device__ __forceinline__ void ldsm_x4(uint32_t (&r)[4], uint32_t addr) {
    asm volatile("ldmatrix.sync.aligned.m8n8.x4.shared.b16 {%0,%1,%2,%3}, [%4];"
                 : "=r"(r[0]), "=r"(r[1]), "=r"(r[2]), "=r"(r[3]) : "r"(addr));
}
__device__ __forceinline__ void mma_bf16(float (&c)[4], const uint32_t (&a)[4],
                                         uint32_t b0, uint32_t b1) {
    asm volatile(
        "mma.sync.aligned.m16n8k16.row.col.f32.bf16.bf16.f32 "
        "{%0,%1,%2,%3}, {%4,%5,%6,%7}, {%8,%9}, {%0,%1,%2,%3};"
        : "+f"(c[0]), "+f"(c[1]), "+f"(c[2]), "+f"(c[3])
        : "r"(a[0]), "r"(a[1]), "r"(a[2]), "r"(a[3]), "r"(b0), "r"(b1));
}
__device__ __forceinline__ uint32_t split2(float x, float y, uint32_t& lo) {
    __nv_bfloat162 h = __floats2bfloat162_rn(x, y);
    __nv_bfloat162 l = __floats2bfloat162_rn(x - __bfloat162float(h.x),
                                             y - __bfloat162float(h.y));
    lo = *(uint32_t*)&l;
    return *(uint32_t*)&h;
}
__device__ __forceinline__ uint32_t sw128(uint32_t off) { return off ^ ((off >> 3) & 0x70); }

// smem stage layout for generic GEMM
#define OFF_AH 0
#define OFF_AL 16384
#define OFF_BH 32768
#define OFF_BL 40960
#define STAGE  49152
#define GEMM_SMEM (2 * STAGE)

// ---------------------------------------------------------------------------
// Generic double-buffered bf16 HMMA GEMM (unchanged from R5)
// ---------------------------------------------------------------------------
__device__ __forceinline__ void load_stage(
    uint32_t sbase, const bf16* Ah, const bf16* Al, const bf16* Bh, const bf16* Bl,
    int lda, int ldb, int m0, int n0, int kbase, int tid)
{
#pragma unroll
    for (int i = 0; i < 4; i++) {
        int c = tid + (i << 8);
        int row = c >> 3, c16 = c & 7;
        uint32_t sw = sw128((row << 7) + (c16 << 4));
        long long src = (long long)(m0 + row) * lda + kbase + (c16 << 3);
        cp16(sbase + OFF_AH + sw, Ah + src);
        cp16(sbase + OFF_AL + sw, Al + src);
    }
#pragma unroll
    for (int i = 0; i < 2; i++) {
        int c = tid + (i << 8);
        int row = c >> 3, c16 = c & 7;
        uint32_t sw = sw128((row << 7) + (c16 << 4));
        long long src = (long long)(n0 + row) * ldb + kbase + (c16 << 3);
        cp16(sbase + OFF_BH + sw, Bh + src);
        cp16(sbase + OFF_BL + sw, Bl + src);
    }
}

__global__ __launch_bounds__(256)
void tc_gemm2(const bf16* __restrict__ Ah, const bf16* __restrict__ Al,
              const bf16* __restrict__ Bh, const bf16* __restrict__ Bl,
              float* __restrict__ Cf, bf16* __restrict__ Ch, bf16* __restrict__ Cl,
              const float* __restrict__ bias,
              int K, int lda, int ldb, int ldc, float alpha, int Hn,
              long long sAb, long long sAh, long long sBb, long long sBh,
              long long sCb, long long sChh)
{
    extern __shared__ char smem[];
    const uint32_t sb = smem_u32(smem);
    const int tid = threadIdx.x, wid = tid >> 5, lane = tid & 31;

    const int z = blockIdx.z;
    const int b = z / Hn, h = z % Hn;
    Ah += b * sAb + h * sAh;  Al += b * sAb + h * sAh;
    Bh += b * sBb + h * sBh;  Bl += b * sBb + h * sBh;
    const long long coff = b * sCb + h * sChh;
    const int m0 = blockIdx.y << 7;
    const int n0 = blockIdx.x << 6;

    const int wm = wid >> 1, wn = wid & 1;

    float acc[2][4][4];
#pragma unroll
    for (int i = 0; i < 2; i++)
#pragma unroll
        for (int j = 0; j < 4; j++)
#pragma unroll
            for (int t = 0; t < 4; t++) acc[i][j][t] = 0.f;

    const uint32_t aRow = (uint32_t)(wm * 32 + (lane & 15));
    const uint32_t aSel = (uint32_t)(((lane >> 4) & 1) * 16);
    const uint32_t bRow = (uint32_t)(wn * 32 + (lane & 7) + ((lane >> 4) & 1) * 8);
    const uint32_t bSel = (uint32_t)(((lane >> 3) & 1) * 16);

    const int nst = K >> 6;
    load_stage(sb, Ah, Al, Bh, Bl, lda, ldb, m0, n0, 0, tid);
    CP_COMMIT();

    for (int s = 0; s < nst; s++) {
        if (s + 1 < nst) {
            load_stage(sb + ((s + 1) & 1) * STAGE, Ah, Al, Bh, Bl, lda, ldb, m0, n0, (s + 1) << 6, tid);
            CP_COMMIT();
            CP_WAIT(1);
        } else {
            CP_WAIT(0);
        }
        __syncthreads();

        const uint32_t st = sb + (s & 1) * STAGE;
#pragma unroll
        for (int kc = 0; kc < 4; kc++) {
            const uint32_t akb = (uint32_t)(kc * 32) + aSel;
            const uint32_t bkb = (uint32_t)(kc * 32) + bSel;
            uint32_t Ahf[2][4], Alf[2][4], Bhf[2][4], Blf[2][4];
#pragma unroll
            for (int mt = 0; mt < 2; mt++) {
                uint32_t sw = sw128(((aRow + mt * 16) << 7) + akb);
                ldsm_x4(Ahf[mt], st + OFF_AH + sw);
                ldsm_x4(Alf[mt], st + OFF_AL + sw);
            }
#pragma unroll
            for (int nb = 0; nb < 2; nb++) {
                uint32_t sw = sw128(((bRow + nb * 16) << 7) + bkb);
                ldsm_x4(Bhf[nb], st + OFF_BH + sw);
                ldsm_x4(Blf[nb], st + OFF_BL + sw);
            }
#pragma unroll
            for (int mt = 0; mt < 2; mt++)
#pragma unroll
                for (int nt = 0; nt < 4; nt++) {
                    const int nb = nt >> 1, sub = (nt & 1) * 2;
                    mma_bf16(acc[mt][nt], Ahf[mt], Bhf[nb][sub], Bhf[nb][sub + 1]);
                    mma_bf16(acc[mt][nt], Ahf[mt], Blf[nb][sub], Blf[nb][sub + 1]);
                    mma_bf16(acc[mt][nt], Alf[mt], Bhf[nb][sub], Bhf[nb][sub + 1]);
                }
        }
        __syncthreads();
    }

    const int g = lane >> 2, tig = lane & 3;
#pragma unroll
    for (int mt = 0; mt < 2; mt++) {
        const int row = m0 + wm * 32 + mt * 16 + g;
#pragma unroll
        for (int nt = 0; nt < 4; nt++) {
            const int col = n0 + wn * 32 + nt * 8 + tig * 2;
            float vx0 = alpha * acc[mt][nt][0], vy0 = alpha * acc[mt][nt][1];
            float vx1 = alpha * acc[mt][nt][2], vy1 = alpha * acc[mt][nt][3];
            if (bias) {
                float2 bv = *reinterpret_cast<const float2*>(bias + col);
                vx0 += bv.x; vy0 += bv.y; vx1 += bv.x; vy1 += bv.y;
            }
            const long long i0 = coff + (long long)row * ldc + col;
            const long long i1 = coff + (long long)(row + 8) * ldc + col;
            if (Cf) {
                *reinterpret_cast<float2*>(Cf + i0) = make_float2(vx0, vy0);
                *reinterpret_cast<float2*>(Cf + i1) = make_float2(vx1, vy1);
            } else {
                uint32_t lo0, lo1;
                uint32_t hi0 = split2(vx0, vy0, lo0);
                uint32_t hi1 = split2(vx1, vy1, lo1);
                *reinterpret_cast<uint32_t*>(Ch + i0) = hi0;
                *reinterpret_cast<uint32_t*>(Cl + i0) = lo0;
                *reinterpret_cast<uint32_t*>(Ch + i1) = hi1;
                *reinterpret_cast<uint32_t*>(Cl + i1) = lo1;
            }
        }
    }
}

// ---------------------------------------------------------------------------
// Specialized logits kernel: per (b,h,q-tile of 128), Q resident, stream K.
// smem: Qh 16K | Ql 16K | stage0 {Bh 8K, Bl 8K} | stage1 {...} = 64KB
// ---------------------------------------------------------------------------
#define LQ_QH 0
#define LQ_QL 16384
#define LQ_ST 32768
#define LQ_STAGE 16384
#define LQ_SMEM 65536

__global__ __launch_bounds__(256)
void logits_k(const bf16* __restrict__ qkvh, const bf16* __restrict__ qkvl,
              float* __restrict__ Cf)
{
    extern __shared__ char smem[];
    const uint32_t sb = smem_u32(smem);
    const int tid = threadIdx.x, wid = tid >> 5, lane = tid & 31;
    const int z = blockIdx.y;                 // b*HH + h
    const int b = z / HH, h = z % HH;
    const int q0 = blockIdx.x << 7;
    const long long qoff = (long long)b * SS * D3 + h * DH;
    const long long koff = qoff + DD;
    float* Cbase = Cf + ((long long)z << 20) + ((long long)q0 << 10);

    const int wm = wid >> 1, wn = wid & 1;
    const uint32_t aRow = (uint32_t)(wm * 32 + (lane & 15));
    const uint32_t aSel = (uint32_t)(((lane >> 4) & 1) * 16);
    const uint32_t bRow = (uint32_t)(wn * 32 + (lane & 7) + ((lane >> 4) & 1) * 8);
    const uint32_t bSel = (uint32_t)(((lane >> 3) & 1) * 16);

    // load Q tile (group 0): 128 rows x 128B, 4 chunks/thread per matrix
#pragma unroll
    for (int i = 0; i < 4; i++) {
        int c = tid + (i << 8);
        int row = c >> 3, c16 = c & 7;
        uint32_t sw = sw128((row << 7) + (c16 << 4));
        long long src = qoff + (long long)(q0 + row) * D3 + (c16 << 3);
        cp16(sb + LQ_QH + sw, qkvh + src);
        cp16(sb + LQ_QL + sw, qkvl + src);
    }
    CP_COMMIT();

    // load K tile 0 into stage 0 (group 1): 64 rows x 128B, 2 chunks/thread/matrix
#pragma unroll
    for (int i = 0; i < 2; i++) {
        int c = tid + (i << 8);
        int row = c >> 3, c16 = c & 7;
        uint32_t sw = sw128((row << 7) + (c16 << 4));
        long long src = koff + (long long)row * D3 + (c16 << 3);
        cp16(sb + LQ_ST + sw, qkvh + src);
        cp16(sb + LQ_ST + 8192 + sw, qkvl + src);
    }
    CP_COMMIT();

    CP_WAIT(1);            // Q ready
    __syncthreads();

    // A-hi fragments resident in registers (A-lo re-read from smem per use)
    uint32_t Ahf[4][2][4];
#pragma unroll
    for (int kc = 0; kc < 4; kc++)
#pragma unroll
        for (int mt = 0; mt < 2; mt++) {
            uint32_t sw = sw128(((aRow + mt * 16) << 7) + (uint32_t)(kc * 32) + aSel);
            ldsm_x4(Ahf[kc][mt], sb + LQ_QH + sw);
        }

    const int g = lane >> 2, tig = lane & 3;

    for (int nt = 0; nt < 16; nt++) {
        if (nt + 1 < 16) {
            const uint32_t st = sb + LQ_ST + ((nt + 1) & 1) * LQ_STAGE;
#pragma unroll
            for (int i = 0; i < 2; i++) {
                int c = tid + (i << 8);
                int row = c >> 3, c16 = c & 7;
                uint32_t sw = sw128((row << 7) + (c16 << 4));
                long long src = koff + (long long)((nt + 1) * 64 + row) * D3 + (c16 << 3);
                cp16(st + sw, qkvh + src);
                cp16(st + 8192 + sw, qkvl + src);
            }
            CP_COMMIT();
            CP_WAIT(1);
        } else {
            CP_WAIT(0);
        }
        __syncthreads();

        const uint32_t st = sb + LQ_ST + (nt & 1) * LQ_STAGE;
        float acc[2][4][4];
#pragma unroll
        for (int i = 0; i < 2; i++)
#pragma unroll
            for (int j = 0; j < 4; j++)
#pragma unroll
                for (int t = 0; t < 4; t++) acc[i][j][t] = 0.f;

#pragma unroll
        for (int kc = 0; kc < 4; kc++) {
            uint32_t Alf[2][4], Bhf[2][4], Blf[2][4];
#pragma unroll
            for (int mt = 0; mt < 2; mt++) {
                uint32_t sw = sw128(((aRow + mt * 16) << 7) + (uint32_t)(kc * 32) + aSel);
                ldsm_x4(Alf[mt], sb + LQ_QL + sw);
            }
#pragma unroll
            for (int nb = 0; nb < 2; nb++) {
                uint32_t sw = sw128(((bRow + nb * 16) << 7) + (uint32_t)(kc * 32) + bSel);
                ldsm_x4(Bhf[nb], st + sw);
                ldsm_x4(Blf[nb], st + 8192 + sw);
            }
#pragma unroll
            for (int mt = 0; mt < 2; mt++)
#pragma unroll
                for (int ntb = 0; ntb < 4; ntb++) {
                    const int nb = ntb >> 1, sub = (ntb & 1) * 2;
                    mma_bf16(acc[mt][ntb], Ahf[kc][mt], Bhf[nb][sub], Bhf[nb][sub + 1]);
                    mma_bf16(acc[mt][ntb], Ahf[kc][mt], Blf[nb][sub], Blf[nb][sub + 1]);
                    mma_bf16(acc[mt][ntb], Alf[mt], Bhf[nb][sub], Bhf[nb][sub + 1]);
                }
        }
        __syncthreads();

        // epilogue for this 128x64 column slab
#pragma unroll
        for (int mt = 0; mt < 2; mt++) {
            const int row = wm * 32 + mt * 16 + g;
#pragma unroll
            for (int ntb = 0; ntb < 4; ntb++) {
                const int col = nt * 64 + wn * 32 + ntb * 8 + tig * 2;
                *reinterpret_cast<float2*>(Cbase + (long long)row * SS + col) =
                    make_float2(0.125f * acc[mt][ntb][0], 0.125f * acc[mt][ntb][1]);
                *reinterpret_cast<float2*>(Cbase + (long long)(row + 8) * SS + col) =
                    make_float2(0.125f * acc[mt][ntb][2], 0.125f * acc[mt][ntb][3]);
            }
        }
    }
}

// ---------------------------------------------------------------------------
// elementwise fp32 -> bf16 hi/lo split
// ---------------------------------------------------------------------------
__global__ __launch_bounds__(256)
void split_k(const float* __restrict__ in, bf16* __restrict__ oh, bf16* __restrict__ ol, int n4)
{
    int i = blockIdx.x * 256 + threadIdx.x;
    if (i >= n4) return;
    float4 f = reinterpret_cast<const float4*>(in)[i];
    uint32_t lo0, lo1;
    uint32_t hi0 = split2(f.x, f.y, lo0);
    uint32_t hi1 = split2(f.z, f.w, lo1);
    reinterpret_cast<uint2*>(oh)[i] = make_uint2(hi0, hi1);
    reinterpret_cast<uint2*>(ol)[i] = make_uint2(lo0, lo1);
}

// ---------------------------------------------------------------------------
// transpose fp32 [R,C] -> bf16 hi/lo [C,R]
// ---------------------------------------------------------------------------
__global__ __launch_bounds__(256)
void transpose_split_k(const float* __restrict__ in, bf16* __restrict__ oh,
                       bf16* __restrict__ ol, int ldi, int ldo)
{
    __shared__ float t[32][33];
    const int r0 = blockIdx.y << 5, c0 = blockIdx.x << 5;
    const int tx = threadIdx.x, ty = threadIdx.y;
#pragma unroll
    for (int i = ty; i < 32; i += 8)
        t[i][tx] = in[(long long)(r0 + i) * ldi + c0 + tx];
    __syncthreads();
#pragma unroll
    for (int i = ty; i < 32; i += 8) {
        float v = t[tx][i];
        bf16 hv = __float2bfloat16(v);
        bf16 lv = __float2bfloat16(v - __bfloat162float(hv));
        long long o = (long long)(c0 + i) * ldo + r0 + tx;
        oh[o] = hv;
        ol[o] = lv;
    }
}

// ---------------------------------------------------------------------------
// batched pair transpose bf16: vT[(b,h),d,s] from qkv hi/lo V block
// ---------------------------------------------------------------------------
__global__ __launch_bounds__(256)
void transpose_pair_k(const bf16* __restrict__ inh, const bf16* __restrict__ inl,
                      bf16* __restrict__ oh, bf16* __restrict__ ol,
                      int ldi, int ldo, int Hn,
                      long long siB, long long siH, long long soB, long long soH)
{
    __shared__ bf16 th[32][33], tl[32][33];
    const int z = blockIdx.z, b = z / Hn, h = z % Hn;
    inh += b * siB + h * siH;  inl += b * siB + h * siH;
    oh  += b * soB + h * soH;  ol  += b * soB + h * soH;
    const int r0 = blockIdx.y << 5, c0 = blockIdx.x << 5;
    const int tx = threadIdx.x, ty = threadIdx.y;
#pragma unroll
    for (int i = ty; i < 32; i += 8) {
        long long s = (long long)(r0 + i) * ldi + c0 + tx;
        th[i][tx] = inh[s];
        tl[i][tx] = inl[s];
    }
    __syncthreads();
#pragma unroll
    for (int i = ty; i < 32; i += 8) {
        long long o = (long long)(c0 + i) * ldo + r0 + tx;
        oh[o] = th[tx][i];
        ol[o] = tl[tx][i];
    }
}

// ---------------------------------------------------------------------------
// Fused talking-heads: pre-mix -> softmax -> post-mix; reads fp32, writes hi/lo
// ---------------------------------------------------------------------------
__global__ __launch_bounds__(256, 4)
void mix_softmax_k(const float* __restrict__ attn,
                   bf16* __restrict__ ah, bf16* __restrict__ al,
                   const float* __restrict__ Wl, const float* __restrict__ bl,
                   const float* __restrict__ Ww, const float* __restrict__ bw)
{
    extern __shared__ float sm[];
    float* sP  = sm;
    float* sWl = sP + HH * SS;
    float* sWw = sWl + HH * HH;
    float* sbl = sWw + HH * HH;
    float* sbw = sbl + HH;

    const int blk = blockIdx.x;
    const int b = blk >> 10, q = blk & 1023;
    const int tid = threadIdx.x;

    for (int i = tid; i < HH * HH; i += 256) { sWl[i] = Wl[i]; sWw[i] = Ww[i]; }
    if (tid < HH) { sbl[tid] = bl[tid]; sbw[tid] = bw[tid]; }
    __syncthreads();

    const long long base = (((long long)b * HH) << 20) + ((long long)q << 10);

    for (int k = tid; k < SS; k += 256) {
        float a[HH];
#pragma unroll
        for (int hh = 0; hh < HH; hh++) a[hh] = attn[base + ((long long)hh << 20) + k];
#pragma unroll
        for (int g = 0; g < HH; g++) {
            float v = sbl[g];
#pragma unroll
            for (int hh = 0; hh < HH; hh++) v = fmaf(a[hh], sWl[hh * HH + g], v);
            sP[g * SS + k] = v;
        }
    }
    __syncthreads();

    const int wid = tid >> 5, lane = tid & 31;
    for (int g = wid; g < HH; g += 8) {
        float* row = sP + g * SS;
        float m = -1e30f;
        for (int k = lane; k < SS; k += 32) m = fmaxf(m, row[k]);
#pragma unroll
        for (int o = 16; o; o >>= 1) m = fmaxf(m, __shfl_xor_sync(0xffffffffu, m, o));
        float s = 0.f;
        for (int k = lane; k < SS; k += 32) {
            float e = __expf(row[k] - m);
            row[k] = e;
            s += e;
        }
#pragma unroll
        for (int o = 16; o; o >>= 1) s += __shfl_xor_sync(0xffffffffu, s, o);
        float inv = 1.f / s;
        for (int k = lane; k < SS; k += 32) row[k] *= inv;
    }
    __syncthreads();

    for (int k = tid; k < SS; k += 256) {
        float p[HH];
#pragma unroll
        for (int hh = 0; hh < HH; hh++) p[hh] = sP[hh * SS + k];
#pragma unroll
        for (int g = 0; g < HH; g++) {
            float v = sbw[g];
#pragma unroll
            for (int hh = 0; hh < HH; hh++) v = fmaf(p[hh], sWw[hh * HH + g], v);
            bf16 hv = __float2bfloat16(v);
            bf16 lv = __float2bfloat16(v - __bfloat162float(hv));
            long long o = base + ((long long)g << 20) + k;
            ah[o] = hv;
            al[o] = lv;
        }
    }
}

// ---------------------------------------------------------------------------
extern "C" void kernel_launch(void* const* d_in, const int* in_sizes, int n_in,
                              void* d_out, int out_size)
{
    const float* x     = (const float*)d_in[0];
    const float* Wqkv  = (const float*)d_in[1];
    const float* bqkv  = (const float*)d_in[2];
    const float* Wl    = (const float*)d_in[3];
    const float* bl    = (const float*)d_in[4];
    const float* Ww    = (const float*)d_in[5];
    const float* bw    = (const float*)d_in[6];
    const float* Wproj = (const float*)d_in[7];
    const float* bproj = (const float*)d_in[8];
    float* out = (float*)d_out;

    bf16 *xh, *xl, *wqh, *wql, *wph, *wpl, *qh, *ql, *vth, *vtl, *ath, *atl, *obh, *obl;
    float* attn;
    cudaGetSymbolAddress((void**)&xh, g_xh);     cudaGetSymbolAddress((void**)&xl, g_xl);
    cudaGetSymbolAddress((void**)&wqh, g_wqkvTh); cudaGetSymbolAddress((void**)&wql, g_wqkvTl);
    cudaGetSymbolAddress((void**)&wph, g_wprojTh); cudaGetSymbolAddress((void**)&wpl, g_wprojTl);
    cudaGetSymbolAddress((void**)&qh, g_qkvh);   cudaGetSymbolAddress((void**)&ql, g_qkvl);
    cudaGetSymbolAddress((void**)&vth, g_vTh);   cudaGetSymbolAddress((void**)&vtl, g_vTl);
    cudaGetSymbolAddress((void**)&attn, g_attn);
    cudaGetSymbolAddress((void**)&ath, g_attnh); cudaGetSymbolAddress((void**)&atl, g_attnl);
    cudaGetSymbolAddress((void**)&obh, g_obufh); cudaGetSymbolAddress((void**)&obl, g_obufl);

    cudaFuncSetAttribute(tc_gemm2, cudaFuncAttributeMaxDynamicSharedMemorySize, GEMM_SMEM);
    cudaFuncSetAttribute(logits_k, cudaFuncAttributeMaxDynamicSharedMemorySize, LQ_SMEM);
    const size_t mix_smem = (HH * SS + 2 * HH * HH + 2 * HH) * sizeof(float);
    cudaFuncSetAttribute(mix_softmax_k, cudaFuncAttributeMaxDynamicSharedMemorySize, (int)mix_smem);

    // 0) operand prep
    split_k<<<(BB * SS * DD / 4 + 255) / 256, 256>>>(x, xh, xl, BB * SS * DD / 4);
    transpose_split_k<<<dim3(D3 / 32, DD / 32), dim3(32, 8)>>>(Wqkv, wqh, wql, D3, DD);
    transpose_split_k<<<dim3(DD / 32, DD / 32), dim3(32, 8)>>>(Wproj, wph, wpl, DD, DD);

    // 1) QKV: x @ WqkvT^T + bqkv -> qkv hi/lo
    tc_gemm2<<<dim3(D3 / 64, 32, 1), 256, GEMM_SMEM>>>(
        xh, xl, wqh, wql, nullptr, qh, ql, bqkv,
        DD, DD, DD, D3, 1.0f, 1, 0, 0, 0, 0, 0, 0);

    // 2) V transpose: qkv[...,1536+h*64+d] -> vT[(b,h),d,s]
    transpose_pair_k<<<dim3(DH / 32, SS / 32, BB * HH), dim3(32, 8)>>>(
        qh + 2 * DD, ql + 2 * DD, vth, vtl, D3, SS, HH,
        (long long)SS * D3, 64,
        (long long)HH * DH * SS, (long long)DH * SS);

    // 3) logits: specialized Q-resident kernel -> attn fp32
    logits_k<<<dim3(SS / 128, BB * HH), 256, LQ_SMEM>>>(qh, ql, attn);

    // 4) pre-mix -> softmax -> post-mix -> attn hi/lo
    mix_softmax_k<<<BB * SS, 256, mix_smem>>>(attn, ath, atl, Wl, bl, Ww, bw);

    // 5) AV: attn @ vT^T -> obuf hi/lo [b,q,h*64+d]
    tc_gemm2<<<dim3(1, SS / 128, BB * HH), 256, GEMM_SMEM>>>(
        ath, atl, vth, vtl, nullptr, obh, obl, nullptr,
        SS, SS, SS, DD, 1.0f, HH,
        (long long)HH * SS * SS, (long long)SS * SS,
        (long long)HH * DH * SS, (long long)DH * SS,
        (long long)SS * DD, 64);

    // 6) proj: obuf @ WprojT^T + bproj -> out fp32
    tc_gemm2<<<dim3(DD / 64, 32, 1), 256, GEMM_SMEM>>>(
        obh, obl, wph, wpl, out, nullptr, nullptr, bproj,
        DD, DD, DD, DD, 1.0f, 1, 0, 0, 0, 0, 0, 0);
}

// round 7
// speedup vs baseline: 2.2275x; 1.0988x over previous
#include <cuda_runtime.h>
#include <cuda_bf16.h>
#include <math.h>
#include <stdint.h>

#define BB 4
#define SS 1024
#define DD 768
#define HH 12
#define DH 64
#define D3 2304

typedef __nv_bfloat16 bf16;

// ---------------- scratch (no runtime allocation) ----------------
__device__ bf16 g_xh[(long long)BB * SS * DD], g_xl[(long long)BB * SS * DD];
__device__ bf16 g_wqkvTh[(long long)D3 * DD], g_wqkvTl[(long long)D3 * DD];
__device__ bf16 g_wprojTh[(long long)DD * DD], g_wprojTl[(long long)DD * DD];
__device__ bf16 g_qkvh[(long long)BB * SS * D3], g_qkvl[(long long)BB * SS * D3];
__device__ bf16 g_vTh[(long long)BB * HH * DH * SS], g_vTl[(long long)BB * HH * DH * SS];
__device__ float g_attn[(long long)BB * HH * SS * SS];
__device__ bf16 g_attnh[(long long)BB * HH * SS * SS], g_attnl[(long long)BB * HH * SS * SS];
__device__ bf16 g_obufh[(long long)BB * SS * DD], g_obufl[(long long)BB * SS * DD];

// ---------------- helpers ----------------
__device__ __forceinline__ uint32_t smem_u32(const void* p) {
    uint32_t a;
    asm("{ .reg .u64 t; cvta.to.shared.u64 t, %1; cvt.u32.u64 %0, t; }" : "=r"(a) : "l"(p));
    return a;
}
__device__ __forceinline__ void cp16(uint32_t dst, const void* src) {
    asm volatile("cp.async.cg.shared.global [%0], [%1], 16;" :: "r"(dst), "l"(src));
}
#define CP_COMMIT() asm volatile("cp.async.commit_group;" ::: "memory")
#define CP_WAIT(n)  asm volatile("cp.async.wait_group %0;" :: "n"(n) : "memory")

__device__ __forceinline__ void ldsm_x4(uint32_t (&r)[4], uint32_t addr) {
    asm volatile("ldmatrix.sync.aligned.m8n8.x4.shared.b16 {%0,%1,%2,%3}, [%4];"
                 : "=r"(r[0]), "=r"(r[1]), "=r"(r[2]), "=r"(r[3]) : "r"(addr));
}
__device__ __forceinline__ void mma_bf16(float (&c)[4], const uint32_t (&a)[4],
                                         uint32_t b0, uint32_t b1) {
    asm volatile(
        "mma.sync.aligned.m16n8k16.row.col.f32.bf16.bf16.f32 "
        "{%0,%1,%2,%3}, {%4,%5,%6,%7}, {%8,%9}, {%0,%1,%2,%3};"
        : "+f"(c[0]), "+f"(c[1]), "+f"(c[2]), "+f"(c[3])
        : "r"(a[0]), "r"(a[1]), "r"(a[2]), "r"(a[3]), "r"(b0), "r"(b1));
}
__device__ __forceinline__ uint32_t split2(float x, float y, uint32_t& lo) {
    __nv_bfloat162 h = __floats2bfloat162_rn(x, y);
    __nv_bfloat162 l = __floats2bfloat162_rn(x - __bfloat162float(h.x),
                                             y - __bfloat162float(h.y));
    lo = *(uint32_t*)&l;
    return *(uint32_t*)&h;
}
__device__ __forceinline__ uint32_t sw128(uint32_t off) { return off ^ ((off >> 3) & 0x70); }

// ======================= generic 128x64 GEMM (AV) =======================
#define OFF_AH 0
#define OFF_AL 16384
#define OFF_BH 32768
#define OFF_BL 40960
#define STAGE  49152
#define GEMM_SMEM (2 * STAGE)

__device__ __forceinline__ void load_stage(
    uint32_t sbase, const bf16* Ah, const bf16* Al, const bf16* Bh, const bf16* Bl,
    int lda, int ldb, int m0, int n0, int kbase, int tid)
{
#pragma unroll
    for (int i = 0; i < 4; i++) {
        int c = tid + (i << 8);
        int row = c >> 3, c16 = c & 7;
        uint32_t sw = sw128((row << 7) + (c16 << 4));
        long long src = (long long)(m0 + row) * lda + kbase + (c16 << 3);
        cp16(sbase + OFF_AH + sw, Ah + src);
        cp16(sbase + OFF_AL + sw, Al + src);
    }
#pragma unroll
    for (int i = 0; i < 2; i++) {
        int c = tid + (i << 8);
        int row = c >> 3, c16 = c & 7;
        uint32_t sw = sw128((row << 7) + (c16 << 4));
        long long src = (long long)(n0 + row) * ldb + kbase + (c16 << 3);
        cp16(sbase + OFF_BH + sw, Bh + src);
        cp16(sbase + OFF_BL + sw, Bl + src);
    }
}

__global__ __launch_bounds__(256)
void tc_gemm2(const bf16* __restrict__ Ah, const bf16* __restrict__ Al,
              const bf16* __restrict__ Bh, const bf16* __restrict__ Bl,
              float* __restrict__ Cf, bf16* __restrict__ Ch, bf16* __restrict__ Cl,
              const float* __restrict__ bias,
              int K, int lda, int ldb, int ldc, float alpha, int Hn,
              long long sAb, long long sAh, long long sBb, long long sBh,
              long long sCb, long long sChh)
{
    extern __shared__ char smem[];
    const uint32_t sb = smem_u32(smem);
    const int tid = threadIdx.x, wid = tid >> 5, lane = tid & 31;

    const int z = blockIdx.z;
    const int b = z / Hn, h = z % Hn;
    Ah += b * sAb + h * sAh;  Al += b * sAb + h * sAh;
    Bh += b * sBb + h * sBh;  Bl += b * sBb + h * sBh;
    const long long coff = b * sCb + h * sChh;
    const int m0 = blockIdx.y << 7;
    const int n0 = blockIdx.x << 6;

    const int wm = wid >> 1, wn = wid & 1;

    float acc[2][4][4];
#pragma unroll
    for (int i = 0; i < 2; i++)
#pragma unroll
        for (int j = 0; j < 4; j++)
#pragma unroll
            for (int t = 0; t < 4; t++) acc[i][j][t] = 0.f;

    const uint32_t aRow = (uint32_t)(wm * 32 + (lane & 15));
    const uint32_t aSel = (uint32_t)(((lane >> 4) & 1) * 16);
    const uint32_t bRow = (uint32_t)(wn * 32 + (lane & 7) + ((lane >> 4) & 1) * 8);
    const uint32_t bSel = (uint32_t)(((lane >> 3) & 1) * 16);

    const int nst = K >> 6;
    load_stage(sb, Ah, Al, Bh, Bl, lda, ldb, m0, n0, 0, tid);
    CP_COMMIT();

    for (int s = 0; s < nst; s++) {
        if (s + 1 < nst) {
            load_stage(sb + ((s + 1) & 1) * STAGE, Ah, Al, Bh, Bl, lda, ldb, m0, n0, (s + 1) << 6, tid);
            CP_COMMIT();
            CP_WAIT(1);
        } else {
            CP_WAIT(0);
        }
        __syncthreads();

        const uint32_t st = sb + (s & 1) * STAGE;
#pragma unroll
        for (int kc = 0; kc < 4; kc++) {
            const uint32_t akb = (uint32_t)(kc * 32) + aSel;
            const uint32_t bkb = (uint32_t)(kc * 32) + bSel;
            uint32_t Ahf[2][4], Alf[2][4], Bhf[2][4], Blf[2][4];
#pragma unroll
            for (int mt = 0; mt < 2; mt++) {
                uint32_t sw = sw128(((aRow + mt * 16) << 7) + akb);
                ldsm_x4(Ahf[mt], st + OFF_AH + sw);
                ldsm_x4(Alf[mt], st + OFF_AL + sw);
            }
#pragma unroll
            for (int nb = 0; nb < 2; nb++) {
                uint32_t sw = sw128(((bRow + nb * 16) << 7) + bkb);
                ldsm_x4(Bhf[nb], st + OFF_BH + sw);
                ldsm_x4(Blf[nb], st + OFF_BL + sw);
            }
#pragma unroll
            for (int mt = 0; mt < 2; mt++)
#pragma unroll
                for (int nt = 0; nt < 4; nt++) {
                    const int nb = nt >> 1, sub = (nt & 1) * 2;
                    mma_bf16(acc[mt][nt], Ahf[mt], Bhf[nb][sub], Bhf[nb][sub + 1]);
                    mma_bf16(acc[mt][nt], Ahf[mt], Blf[nb][sub], Blf[nb][sub + 1]);
                    mma_bf16(acc[mt][nt], Alf[mt], Bhf[nb][sub], Bhf[nb][sub + 1]);
                }
        }
        __syncthreads();
    }

    const int g = lane >> 2, tig = lane & 3;
#pragma unroll
    for (int mt = 0; mt < 2; mt++) {
        const int row = m0 + wm * 32 + mt * 16 + g;
#pragma unroll
        for (int nt = 0; nt < 4; nt++) {
            const int col = n0 + wn * 32 + nt * 8 + tig * 2;
            float vx0 = alpha * acc[mt][nt][0], vy0 = alpha * acc[mt][nt][1];
            float vx1 = alpha * acc[mt][nt][2], vy1 = alpha * acc[mt][nt][3];
            if (bias) {
                float2 bv = *reinterpret_cast<const float2*>(bias + col);
                vx0 += bv.x; vy0 += bv.y; vx1 += bv.x; vy1 += bv.y;
            }
            const long long i0 = coff + (long long)row * ldc + col;
            const long long i1 = coff + (long long)(row + 8) * ldc + col;
            if (Cf) {
                *reinterpret_cast<float2*>(Cf + i0) = make_float2(vx0, vy0);
                *reinterpret_cast<float2*>(Cf + i1) = make_float2(vx1, vy1);
            } else {
                uint32_t lo0, lo1;
                uint32_t hi0 = split2(vx0, vy0, lo0);
                uint32_t hi1 = split2(vx1, vy1, lo1);
                *reinterpret_cast<uint32_t*>(Ch + i0) = hi0;
                *reinterpret_cast<uint32_t*>(Cl + i0) = lo0;
                *reinterpret_cast<uint32_t*>(Ch + i1) = hi1;
                *reinterpret_cast<uint32_t*>(Cl + i1) = lo1;
            }
        }
    }
}

// ======================= 128x128 GEMM (QKV, proj) =======================
#define O3_AH 0
#define O3_AL 16384
#define O3_BH 32768
#define O3_BL 49152
#define STAGE3 65536
#define GEMM3_SMEM (2 * STAGE3)

__device__ __forceinline__ void load_stage3(
    uint32_t sbase, const bf16* Ah, const bf16* Al, const bf16* Bh, const bf16* Bl,
    int lda, int ldb, int m0, int n0, int kbase, int tid)
{
#pragma unroll
    for (int i = 0; i < 4; i++) {
        int c = tid + (i << 8);
        int row = c >> 3, c16 = c & 7;
        uint32_t sw = sw128((row << 7) + (c16 << 4));
        long long asrc = (long long)(m0 + row) * lda + kbase + (c16 << 3);
        long long bsrc = (long long)(n0 + row) * ldb + kbase + (c16 << 3);
        cp16(sbase + O3_AH + sw, Ah + asrc);
        cp16(sbase + O3_AL + sw, Al + asrc);
        cp16(sbase + O3_BH + sw, Bh + bsrc);
        cp16(sbase + O3_BL + sw, Bl + bsrc);
    }
}

__global__ __launch_bounds__(256)
void tc_gemm3(const bf16* __restrict__ Ah, const bf16* __restrict__ Al,
              const bf16* __restrict__ Bh, const bf16* __restrict__ Bl,
              float* __restrict__ Cf, bf16* __restrict__ Ch, bf16* __restrict__ Cl,
              const float* __restrict__ bias,
              int K, int lda, int ldb, int ldc)
{
    extern __shared__ char smem[];
    const uint32_t sb = smem_u32(smem);
    const int tid = threadIdx.x, wid = tid >> 5, lane = tid & 31;
    const int m0 = blockIdx.y << 7;
    const int n0 = blockIdx.x << 7;

    const int wm = wid >> 2;          // 0..1 -> 64-row slab
    const int wn = wid & 3;           // 0..3 -> 32-col slab

    float acc[4][4][4];
#pragma unroll
    for (int i = 0; i < 4; i++)
#pragma unroll
        for (int j = 0; j < 4; j++)
#pragma unroll
            for (int t = 0; t < 4; t++) acc[i][j][t] = 0.f;

    const uint32_t aRow = (uint32_t)(wm * 64 + (lane & 15));
    const uint32_t aSel = (uint32_t)(((lane >> 4) & 1) * 16);
    const uint32_t bRow = (uint32_t)(wn * 32 + (lane & 7) + ((lane >> 4) & 1) * 8);
    const uint32_t bSel = (uint32_t)(((lane >> 3) & 1) * 16);

    const int nst = K >> 6;
    load_stage3(sb, Ah, Al, Bh, Bl, lda, ldb, m0, n0, 0, tid);
    CP_COMMIT();

    for (int s = 0; s < nst; s++) {
        if (s + 1 < nst) {
            load_stage3(sb + ((s + 1) & 1) * STAGE3, Ah, Al, Bh, Bl, lda, ldb, m0, n0, (s + 1) << 6, tid);
            CP_COMMIT();
            CP_WAIT(1);
        } else {
            CP_WAIT(0);
        }
        __syncthreads();

        const uint32_t st = sb + (s & 1) * STAGE3;
#pragma unroll
        for (int kc = 0; kc < 4; kc++) {
            const uint32_t akb = (uint32_t)(kc * 32) + aSel;
            const uint32_t bkb = (uint32_t)(kc * 32) + bSel;
            uint32_t Ahf[4][4], Alf[4][4], Bhf[2][4], Blf[2][4];
#pragma unroll
            for (int mt = 0; mt < 4; mt++) {
                uint32_t sw = sw128(((aRow + mt * 16) << 7) + akb);
                ldsm_x4(Ahf[mt], st + O3_AH + sw);
                ldsm_x4(Alf[mt], st + O3_AL + sw);
            }
#pragma unroll
            for (int nb = 0; nb < 2; nb++) {
                uint32_t sw = sw128(((bRow + nb * 16) << 7) + bkb);
                ldsm_x4(Bhf[nb], st + O3_BH + sw);
                ldsm_x4(Blf[nb], st + O3_BL + sw);
            }
#pragma unroll
            for (int mt = 0; mt < 4; mt++)
#pragma unroll
                for (int nt = 0; nt < 4; nt++) {
                    const int nb = nt >> 1, sub = (nt & 1) * 2;
                    mma_bf16(acc[mt][nt], Ahf[mt], Bhf[nb][sub], Bhf[nb][sub + 1]);
                    mma_bf16(acc[mt][nt], Ahf[mt], Blf[nb][sub], Blf[nb][sub + 1]);
                    mma_bf16(acc[mt][nt], Alf[mt], Bhf[nb][sub], Bhf[nb][sub + 1]);
                }
        }
        __syncthreads();
    }

    const int g = lane >> 2, tig = lane & 3;
#pragma unroll
    for (int mt = 0; mt < 4; mt++) {
        const int row = m0 + wm * 64 + mt * 16 + g;
#pragma unroll
        for (int nt = 0; nt < 4; nt++) {
            const int col = n0 + wn * 32 + nt * 8 + tig * 2;
            float vx0 = acc[mt][nt][0], vy0 = acc[mt][nt][1];
            float vx1 = acc[mt][nt][2], vy1 = acc[mt][nt][3];
            if (bias) {
                float2 bv = *reinterpret_cast<const float2*>(bias + col);
                vx0 += bv.x; vy0 += bv.y; vx1 += bv.x; vy1 += bv.y;
            }
            const long long i0 = (long long)row * ldc + col;
            const long long i1 = (long long)(row + 8) * ldc + col;
            if (Cf) {
                *reinterpret_cast<float2*>(Cf + i0) = make_float2(vx0, vy0);
                *reinterpret_cast<float2*>(Cf + i1) = make_float2(vx1, vy1);
            } else {
                uint32_t lo0, lo1;
                uint32_t hi0 = split2(vx0, vy0, lo0);
                uint32_t hi1 = split2(vx1, vy1, lo1);
                *reinterpret_cast<uint32_t*>(Ch + i0) = hi0;
                *reinterpret_cast<uint32_t*>(Cl + i0) = lo0;
                *reinterpret_cast<uint32_t*>(Ch + i1) = hi1;
                *reinterpret_cast<uint32_t*>(Cl + i1) = lo1;
            }
        }
    }
}

// ======================= logits (Q-resident) =======================
#define LQ_QH 0
#define LQ_QL 16384
#define LQ_ST 32768
#define LQ_STAGE 16384
#define LQ_SMEM 65536

__global__ __launch_bounds__(256)
void logits_k(const bf16* __restrict__ qkvh, const bf16* __restrict__ qkvl,
              float* __restrict__ Cf)
{
    extern __shared__ char smem[];
    const uint32_t sb = smem_u32(smem);
    const int tid = threadIdx.x, wid = tid >> 5, lane = tid & 31;
    const int z = blockIdx.y;
    const int b = z / HH, h = z % HH;
    const int q0 = blockIdx.x << 7;
    const long long qoff = (long long)b * SS * D3 + h * DH;
    const long long koff = qoff + DD;
    float* Cbase = Cf + ((long long)z << 20) + ((long long)q0 << 10);

    const int wm = wid >> 1, wn = wid & 1;
    const uint32_t aRow = (uint32_t)(wm * 32 + (lane & 15));
    const uint32_t aSel = (uint32_t)(((lane >> 4) & 1) * 16);
    const uint32_t bRow = (uint32_t)(wn * 32 + (lane & 7) + ((lane >> 4) & 1) * 8);
    const uint32_t bSel = (uint32_t)(((lane >> 3) & 1) * 16);

#pragma unroll
    for (int i = 0; i < 4; i++) {
        int c = tid + (i << 8);
        int row = c >> 3, c16 = c & 7;
        uint32_t sw = sw128((row << 7) + (c16 << 4));
        long long src = qoff + (long long)(q0 + row) * D3 + (c16 << 3);
        cp16(sb + LQ_QH + sw, qkvh + src);
        cp16(sb + LQ_QL + sw, qkvl + src);
    }
    CP_COMMIT();

#pragma unroll
    for (int i = 0; i < 2; i++) {
        int c = tid + (i << 8);
        int row = c >> 3, c16 = c & 7;
        uint32_t sw = sw128((row << 7) + (c16 << 4));
        long long src = koff + (long long)row * D3 + (c16 << 3);
        cp16(sb + LQ_ST + sw, qkvh + src);
        cp16(sb + LQ_ST + 8192 + sw, qkvl + src);
    }
    CP_COMMIT();

    CP_WAIT(1);
    __syncthreads();

    uint32_t Ahf[4][2][4];
#pragma unroll
    for (int kc = 0; kc < 4; kc++)
#pragma unroll
        for (int mt = 0; mt < 2; mt++) {
            uint32_t sw = sw128(((aRow + mt * 16) << 7) + (uint32_t)(kc * 32) + aSel);
            ldsm_x4(Ahf[kc][mt], sb + LQ_QH + sw);
        }

    const int g = lane >> 2, tig = lane & 3;

    for (int nt = 0; nt < 16; nt++) {
        if (nt + 1 < 16) {
            const uint32_t st = sb + LQ_ST + ((nt + 1) & 1) * LQ_STAGE;
#pragma unroll
            for (int i = 0; i < 2; i++) {
                int c = tid + (i << 8);
                int row = c >> 3, c16 = c & 7;
                uint32_t sw = sw128((row << 7) + (c16 << 4));
                long long src = koff + (long long)((nt + 1) * 64 + row) * D3 + (c16 << 3);
                cp16(st + sw, qkvh + src);
                cp16(st + 8192 + sw, qkvl + src);
            }
            CP_COMMIT();
            CP_WAIT(1);
        } else {
            CP_WAIT(0);
        }
        __syncthreads();

        const uint32_t st = sb + LQ_ST + (nt & 1) * LQ_STAGE;
        float acc[2][4][4];
#pragma unroll
        for (int i = 0; i < 2; i++)
#pragma unroll
            for (int j = 0; j < 4; j++)
#pragma unroll
                for (int t = 0; t < 4; t++) acc[i][j][t] = 0.f;

#pragma unroll
        for (int kc = 0; kc < 4; kc++) {
            uint32_t Alf[2][4], Bhf[2][4], Blf[2][4];
#pragma unroll
            for (int mt = 0; mt < 2; mt++) {
                uint32_t sw = sw128(((aRow + mt * 16) << 7) + (uint32_t)(kc * 32) + aSel);
                ldsm_x4(Alf[mt], sb + LQ_QL + sw);
            }
#pragma unroll
            for (int nb = 0; nb < 2; nb++) {
                uint32_t sw = sw128(((bRow + nb * 16) << 7) + (uint32_t)(kc * 32) + bSel);
                ldsm_x4(Bhf[nb], st + sw);
                ldsm_x4(Blf[nb], st + 8192 + sw);
            }
#pragma unroll
            for (int mt = 0; mt < 2; mt++)
#pragma unroll
                for (int ntb = 0; ntb < 4; ntb++) {
                    const int nb = ntb >> 1, sub = (ntb & 1) * 2;
                    mma_bf16(acc[mt][ntb], Ahf[kc][mt], Bhf[nb][sub], Bhf[nb][sub + 1]);
                    mma_bf16(acc[mt][ntb], Ahf[kc][mt], Blf[nb][sub], Blf[nb][sub + 1]);
                    mma_bf16(acc[mt][ntb], Alf[mt], Bhf[nb][sub], Bhf[nb][sub + 1]);
                }
        }
        __syncthreads();

#pragma unroll
        for (int mt = 0; mt < 2; mt++) {
            const int row = wm * 32 + mt * 16 + g;
#pragma unroll
            for (int ntb = 0; ntb < 4; ntb++) {
                const int col = nt * 64 + wn * 32 + ntb * 8 + tig * 2;
                *reinterpret_cast<float2*>(Cbase + (long long)row * SS + col) =
                    make_float2(0.125f * acc[mt][ntb][0], 0.125f * acc[mt][ntb][1]);
                *reinterpret_cast<float2*>(Cbase + (long long)(row + 8) * SS + col) =
                    make_float2(0.125f * acc[mt][ntb][2], 0.125f * acc[mt][ntb][3]);
            }
        }
    }
}

// ======================= prep kernels =======================
__global__ __launch_bounds__(256)
void split_k(const float* __restrict__ in, bf16* __restrict__ oh, bf16* __restrict__ ol, int n4)
{
    int i = blockIdx.x * 256 + threadIdx.x;
    if (i >= n4) return;
    float4 f = reinterpret_cast<const float4*>(in)[i];
    uint32_t lo0, lo1;
    uint32_t hi0 = split2(f.x, f.y, lo0);
    uint32_t hi1 = split2(f.z, f.w, lo1);
    reinterpret_cast<uint2*>(oh)[i] = make_uint2(hi0, hi1);
    reinterpret_cast<uint2*>(ol)[i] = make_uint2(lo0, lo1);
}

__global__ __launch_bounds__(256)
void transpose_split_k(const float* __restrict__ in, bf16* __restrict__ oh,
                       bf16* __restrict__ ol, int ldi, int ldo)
{
    __shared__ float t[32][33];
    const int r0 = blockIdx.y << 5, c0 = blockIdx.x << 5;
    const int tx = threadIdx.x, ty = threadIdx.y;
#pragma unroll
    for (int i = ty; i < 32; i += 8)
        t[i][tx] = in[(long long)(r0 + i) * ldi + c0 + tx];
    __syncthreads();
#pragma unroll
    for (int i = ty; i < 32; i += 8) {
        float v = t[tx][i];
        bf16 hv = __float2bfloat16(v);
        bf16 lv = __float2bfloat16(v - __bfloat162float(hv));
        long long o = (long long)(c0 + i) * ldo + r0 + tx;
        oh[o] = hv;
        ol[o] = lv;
    }
}

__global__ __launch_bounds__(256)
void transpose_pair_k(const bf16* __restrict__ inh, const bf16* __restrict__ inl,
                      bf16* __restrict__ oh, bf16* __restrict__ ol,
                      int ldi, int ldo, int Hn,
                      long long siB, long long siH, long long soB, long long soH)
{
    __shared__ bf16 th[32][33], tl[32][33];
    const int z = blockIdx.z, b = z / Hn, h = z % Hn;
    inh += b * siB + h * siH;  inl += b * siB + h * siH;
    oh  += b * soB + h * soH;  ol  += b * soB + h * soH;
    const int r0 = blockIdx.y << 5, c0 = blockIdx.x << 5;
    const int tx = threadIdx.x, ty = threadIdx.y;
#pragma unroll
    for (int i = ty; i < 32; i += 8) {
        long long s = (long long)(r0 + i) * ldi + c0 + tx;
        th[i][tx] = inh[s];
        tl[i][tx] = inl[s];
    }
    __syncthreads();
#pragma unroll
    for (int i = ty; i < 32; i += 8) {
        long long o = (long long)(c0 + i) * ldo + r0 + tx;
        oh[o] = th[tx][i];
        ol[o] = tl[tx][i];
    }
}

// ======================= fused mix/softmax/mix =======================
__global__ __launch_bounds__(256, 4)
void mix_softmax_k(const float* __restrict__ attn,
                   bf16* __restrict__ ah, bf16* __restrict__ al,
                   const float* __restrict__ Wl, const float* __restrict__ bl,
                   const float* __restrict__ Ww, const float* __restrict__ bw)
{
    extern __shared__ float sm[];
    float* sP  = sm;
    float* sWl = sP + HH * SS;
    float* sWw = sWl + HH * HH;
    float* sbl = sWw + HH * HH;
    float* sbw = sbl + HH;

    const int blk = blockIdx.x;
    const int b = blk >> 10, q = blk & 1023;
    const int tid = threadIdx.x;

    for (int i = tid; i < HH * HH; i += 256) { sWl[i] = Wl[i]; sWw[i] = Ww[i]; }
    if (tid < HH) { sbl[tid] = bl[tid]; sbw[tid] = bw[tid]; }
    __syncthreads();

    const long long base = (((long long)b * HH) << 20) + ((long long)q << 10);

    // pre-mix, 2 k per thread, float2 IO
#pragma unroll
    for (int it = 0; it < 2; it++) {
        const int k = (tid + (it << 8)) << 1;
        float2 a[HH];
#pragma unroll
        for (int hh = 0; hh < HH; hh++)
            a[hh] = *reinterpret_cast<const float2*>(attn + base + ((long long)hh << 20) + k);
#pragma unroll
        for (int g = 0; g < HH; g++) {
            float v0 = sbl[g], v1 = sbl[g];
#pragma unroll
            for (int hh = 0; hh < HH; hh++) {
                float w = sWl[hh * HH + g];
                v0 = fmaf(a[hh].x, w, v0);
                v1 = fmaf(a[hh].y, w, v1);
            }
            *reinterpret_cast<float2*>(sP + g * SS + k) = make_float2(v0, v1);
        }
    }
    __syncthreads();

    // softmax per row
    const int wid = tid >> 5, lane = tid & 31;
    for (int g = wid; g < HH; g += 8) {
        float* row = sP + g * SS;
        float m = -1e30f;
        for (int k = lane; k < SS; k += 32) m = fmaxf(m, row[k]);
#pragma unroll
        for (int o = 16; o; o >>= 1) m = fmaxf(m, __shfl_xor_sync(0xffffffffu, m, o));
        float s = 0.f;
        for (int k = lane; k < SS; k += 32) {
            float e = __expf(row[k] - m);
            row[k] = e;
            s += e;
        }
#pragma unroll
        for (int o = 16; o; o >>= 1) s += __shfl_xor_sync(0xffffffffu, s, o);
        float inv = 1.f / s;
        for (int k = lane; k < SS; k += 32) row[k] *= inv;
    }
    __syncthreads();

    // post-mix + packed hi/lo writeback
#pragma unroll
    for (int it = 0; it < 2; it++) {
        const int k = (tid + (it << 8)) << 1;
        float2 p[HH];
#pragma unroll
        for (int hh = 0; hh < HH; hh++)
            p[hh] = *reinterpret_cast<const float2*>(sP + hh * SS + k);
#pragma unroll
        for (int g = 0; g < HH; g++) {
            float v0 = sbw[g], v1 = sbw[g];
#pragma unroll
            for (int hh = 0; hh < HH; hh++) {
                float w = sWw[hh * HH + g];
                v0 = fmaf(p[hh].x, w, v0);
                v1 = fmaf(p[hh].y, w, v1);
            }
            uint32_t lo;
            uint32_t hi = split2(v0, v1, lo);
            const long long o = base + ((long long)g << 20) + k;
            *reinterpret_cast<uint32_t*>(ah + o) = hi;
            *reinterpret_cast<uint32_t*>(al + o) = lo;
        }
    }
}

// ---------------------------------------------------------------------------
extern "C" void kernel_launch(void* const* d_in, const int* in_sizes, int n_in,
                              void* d_out, int out_size)
{
    const float* x     = (const float*)d_in[0];
    const float* Wqkv  = (const float*)d_in[1];
    const float* bqkv  = (const float*)d_in[2];
    const float* Wl    = (const float*)d_in[3];
    const float* bl    = (const float*)d_in[4];
    const float* Ww    = (const float*)d_in[5];
    const float* bw    = (const float*)d_in[6];
    const float* Wproj = (const float*)d_in[7];
    const float* bproj = (const float*)d_in[8];
    float* out = (float*)d_out;

    bf16 *xh, *xl, *wqh, *wql, *wph, *wpl, *qh, *ql, *vth, *vtl, *ath, *atl, *obh, *obl;
    float* attn;
    cudaGetSymbolAddress((void**)&xh, g_xh);     cudaGetSymbolAddress((void**)&xl, g_xl);
    cudaGetSymbolAddress((void**)&wqh, g_wqkvTh); cudaGetSymbolAddress((void**)&wql, g_wqkvTl);
    cudaGetSymbolAddress((void**)&wph, g_wprojTh); cudaGetSymbolAddress((void**)&wpl, g_wprojTl);
    cudaGetSymbolAddress((void**)&qh, g_qkvh);   cudaGetSymbolAddress((void**)&ql, g_qkvl);
    cudaGetSymbolAddress((void**)&vth, g_vTh);   cudaGetSymbolAddress((void**)&vtl, g_vTl);
    cudaGetSymbolAddress((void**)&attn, g_attn);
    cudaGetSymbolAddress((void**)&ath, g_attnh); cudaGetSymbolAddress((void**)&atl, g_attnl);
    cudaGetSymbolAddress((void**)&obh, g_obufh); cudaGetSymbolAddress((void**)&obl, g_obufl);

    cudaFuncSetAttribute(tc_gemm2, cudaFuncAttributeMaxDynamicSharedMemorySize, GEMM_SMEM);
    cudaFuncSetAttribute(tc_gemm3, cudaFuncAttributeMaxDynamicSharedMemorySize, GEMM3_SMEM);
    cudaFuncSetAttribute(logits_k, cudaFuncAttributeMaxDynamicSharedMemorySize, LQ_SMEM);
    const size_t mix_smem = (HH * SS + 2 * HH * HH + 2 * HH) * sizeof(float);
    cudaFuncSetAttribute(mix_softmax_k, cudaFuncAttributeMaxDynamicSharedMemorySize, (int)mix_smem);

    // 0) operand prep
    split_k<<<(BB * SS * DD / 4 + 255) / 256, 256>>>(x, xh, xl, BB * SS * DD / 4);
    transpose_split_k<<<dim3(D3 / 32, DD / 32), dim3(32, 8)>>>(Wqkv, wqh, wql, D3, DD);
    transpose_split_k<<<dim3(DD / 32, DD / 32), dim3(32, 8)>>>(Wproj, wph, wpl, DD, DD);

    // 1) QKV: x @ WqkvT^T + bqkv -> qkv hi/lo   (128x128 tiles)
    tc_gemm3<<<dim3(D3 / 128, 32, 1), 256, GEMM3_SMEM>>>(
        xh, xl, wqh, wql, nullptr, qh, ql, bqkv, DD, DD, DD, D3);

    // 2) V transpose
    transpose_pair_k<<<dim3(DH / 32, SS / 32, BB * HH), dim3(32, 8)>>>(
        qh + 2 * DD, ql + 2 * DD, vth, vtl, D3, SS, HH,
        (long long)SS * D3, 64,
        (long long)HH * DH * SS, (long long)DH * SS);

    // 3) logits -> attn fp32
    logits_k<<<dim3(SS / 128, BB * HH), 256, LQ_SMEM>>>(qh, ql, attn);

    // 4) mix -> softmax -> mix -> attn hi/lo
    mix_softmax_k<<<BB * SS, 256, mix_smem>>>(attn, ath, atl, Wl, bl, Ww, bw);

    // 5) AV: attn @ vT^T -> obuf hi/lo
    tc_gemm2<<<dim3(1, SS / 128, BB * HH), 256, GEMM_SMEM>>>(
        ath, atl, vth, vtl, nullptr, obh, obl, nullptr,
        SS, SS, SS, DD, 1.0f, HH,
        (long long)HH * SS * SS, (long long)SS * SS,
        (long long)HH * DH * SS, (long long)DH * SS,
        (long long)SS * DD, 64);

    // 6) proj: obuf @ WprojT^T + bproj -> out fp32   (128x128 tiles)
    tc_gemm3<<<dim3(DD / 128, 32, 1), 256, GEMM3_SMEM>>>(
        obh, obl, wph, wpl, out, nullptr, nullptr, bproj, DD, DD, DD, DD);
}